// round 12
// baseline (speedup 1.0000x reference)
#include <cuda_runtime.h>
#include <cuda_fp16.h>
#include <cstdint>
#include <cstddef>
#include <math.h>

#define NTOK 8192
#define Hd 2048
#define Id 1024
#define Pd 4096
#define Dd 1024

// ---------------- static device scratch (fp16 splits) ----------------
__device__ __half g_xa0[(size_t)NTOK * Hd];
__device__ __half g_xa1[(size_t)NTOK * Hd];
__device__ __half g_w1t0[(size_t)Id * Hd];
__device__ __half g_w1t1[(size_t)Id * Hd];
__device__ __half g_i0[(size_t)NTOK * Id];
__device__ __half g_w2t0[(size_t)Pd * Id];
__device__ float  g_w2tf[(size_t)Pd * Id];
__device__ __half g_wpt0[(size_t)Dd * Hd];
__device__ __half g_ca0[(size_t)NTOK * 2 * Dd];
__device__ __half g_ca1[(size_t)NTOK * 2 * Dd];
__device__ __half g_wmt0[(size_t)Dd * 2 * Dd];
__device__ __half g_lb[(size_t)NTOK * Pd];      // fp16 logits
__device__ float  g_inter[(size_t)NTOK * Id];
__device__ float  g_proj[(size_t)NTOK * Dd];
__device__ float  g_usage[Pd];

__device__ __forceinline__ __half* bufselw(int s) {
    switch (s) {
        case 0:  return g_xa0;  case 1:  return g_xa1;
        case 3:  return g_w1t0; case 4:  return g_w1t1;
        case 6:  return g_i0;   case 7:  return g_w2t0;
        case 8:  return g_wpt0;
        case 10: return g_ca0;  case 11: return g_ca1;
        default: return g_wmt0;
    }
}
__device__ __forceinline__ const __half* bufsel(int s) { return bufselw(s); }
__device__ __forceinline__ float* csel(int s, float* ext) {
    switch (s) {
        case 0: return g_inter;
        case 2: return g_proj;
        default: return ext;
    }
}

// ---------------- PTX helpers ----------------
__device__ __forceinline__ uint32_t smem_u32(const void* p) {
    uint32_t a;
    asm("{ .reg .u64 t; cvta.to.shared.u64 t, %1; cvt.u32.u64 %0, t; }" : "=r"(a) : "l"(p));
    return a;
}
#define CPA16(d, s) asm volatile("cp.async.cg.shared.global [%0], [%1], 16;" :: "r"(d), "l"(s) : "memory")
#define CPA_COMMIT() asm volatile("cp.async.commit_group;" ::: "memory")
#define CPA_WAIT4() asm volatile("cp.async.wait_group 4;" ::: "memory")
#define CPA_WAIT3() asm volatile("cp.async.wait_group 3;" ::: "memory")
#define CPA_WAIT2() asm volatile("cp.async.wait_group 2;" ::: "memory")
#define CPA_WAIT1() asm volatile("cp.async.wait_group 1;" ::: "memory")
#define CPA_WAIT0() asm volatile("cp.async.wait_group 0;" ::: "memory")

__device__ __forceinline__ void ldmx4(uint32_t* r, uint32_t addr) {
    asm volatile("ldmatrix.sync.aligned.m8n8.x4.shared.b16 {%0,%1,%2,%3}, [%4];"
                 : "=r"(r[0]), "=r"(r[1]), "=r"(r[2]), "=r"(r[3]) : "r"(addr));
}
__device__ __forceinline__ void mma16816(float* d, const uint32_t* a, const uint32_t* b) {
    asm volatile("mma.sync.aligned.m16n8k16.row.col.f32.f16.f16.f32 "
                 "{%0,%1,%2,%3}, {%4,%5,%6,%7}, {%8,%9}, {%0,%1,%2,%3};"
                 : "+f"(d[0]), "+f"(d[1]), "+f"(d[2]), "+f"(d[3])
                 : "r"(a[0]), "r"(a[1]), "r"(a[2]), "r"(a[3]), "r"(b[0]), "r"(b[1]));
}

// ---------------- HMMA GEMM: D[M,N] = sum_p A_p @ B_p^T + bias --------------
// Tile 128x128, BK=32, 5-stage DYNAMIC smem pipeline (80 KB), 2 CTAs/SM.
#define ST 5
#define STAGE_B 16384       // A 8KB + B 8KB
#define SMEM_DYN (ST * STAGE_B)

__device__ __forceinline__ uint32_t swzo(int row, int kcol) {
    return (uint32_t)(row * 64 + ((((kcol >> 3) ^ ((row >> 1) & 3)) << 4)) + ((kcol & 7) << 1));
}

__global__ void __launch_bounds__(256, 2)
gemm_mma(uint32_t aPack, uint32_t bPack, int npass, int K,
         const float* __restrict__ bias, float* Cext, int cselv, int ldc,
         int relu, int conv)   // conv: 0 none, 1 also fp16->g_i0, 2 fp16 ONLY ->g_lb
{
    extern __shared__ __align__(1024) char smem[];
    const uint32_t sb = smem_u32(smem);
    const int tid = threadIdx.x, lane = tid & 31, wid = tid >> 5;
    const int wm = wid & 1, wn = wid >> 1;          // warp grid 2(M) x 4(N)
    const int bn = blockIdx.x, bm = blockIdx.y;
    float* C = csel(cselv, Cext);

    const int kcp = K >> 5;
    const int NCH = npass * kcp;

    float acc[4][4][4];
    #pragma unroll
    for (int i = 0; i < 4; i++)
        #pragma unroll
        for (int j = 0; j < 4; j++)
            #pragma unroll
            for (int q = 0; q < 4; q++) acc[i][j][q] = 0.0f;

    auto load_chunk = [&](int ch, int buf) {
        const int p = ch / kcp, kc = ch % kcp;
        const __half* A = bufsel((aPack >> (4 * p)) & 15) + (size_t)(bm * 128) * K + kc * 32;
        const __half* B = bufsel((bPack >> (4 * p)) & 15) + (size_t)(bn * 128) * K + kc * 32;
        const uint32_t ab = sb + buf * STAGE_B;
        const uint32_t bb = ab + 8192;
        #pragma unroll
        for (int i = 0; i < 2; i++) {
            const int g = tid + i * 256, r = g >> 2, c = g & 3;
            const uint32_t so = swzo(r, c * 8);
            CPA16(ab + so, A + (size_t)r * K + c * 8);
            CPA16(bb + so, B + (size_t)r * K + c * 8);
        }
        CPA_COMMIT();
    };

    // prologue: fill 4 stages
    #pragma unroll
    for (int s = 0; s < ST - 1; s++)
        if (s < NCH) load_chunk(s, s);

    const int a_r = wm * 64 + (lane & 15);                      // + mt*16
    const int a_kc = (lane >> 4) * 8;                           // + ks*16
    const int b_r = wn * 32 + (lane & 7) + ((lane >> 4) << 3);  // + q*16
    const int b_kc = ((lane >> 3) & 1) * 8;                     // + ks*16

    for (int c = 0; c < NCH; c++) {
        if (c + ST - 1 < NCH) {
            load_chunk(c + ST - 1, (c + ST - 1) % ST);  // buf (c-1)%ST: readers done at prev tail sync
            CPA_WAIT4();
        } else {
            const int rem = NCH - 1 - c;   // groups still pending after c completes
            if (rem >= 3) CPA_WAIT3();
            else if (rem == 2) CPA_WAIT2();
            else if (rem == 1) CPA_WAIT1();
            else CPA_WAIT0();
        }
        __syncthreads();                   // chunk c visible to all warps

        const uint32_t abase = sb + (c % ST) * STAGE_B;
        const uint32_t bbase = abase + 8192;
        #pragma unroll
        for (int ks = 0; ks < 2; ks++) {
            uint32_t af[4][4], bf[2][4];
            #pragma unroll
            for (int mt = 0; mt < 4; mt++)
                ldmx4(af[mt], abase + swzo(a_r + mt * 16, ks * 16 + a_kc));
            #pragma unroll
            for (int q = 0; q < 2; q++)
                ldmx4(bf[q], bbase + swzo(b_r + q * 16, ks * 16 + b_kc));
            #pragma unroll
            for (int mt = 0; mt < 4; mt++)
                #pragma unroll
                for (int nt = 0; nt < 4; nt++)
                    mma16816(acc[mt][nt], af[mt], &bf[nt >> 1][(nt & 1) * 2]);
        }
        __syncthreads();                   // reads of chunk c done before buffer reuse
    }

    #pragma unroll
    for (int mt = 0; mt < 4; mt++) {
        const int r0 = bm * 128 + wm * 64 + mt * 16 + (lane >> 2);
        #pragma unroll
        for (int nt = 0; nt < 4; nt++) {
            const int col = bn * 128 + wn * 32 + nt * 8 + (lane & 3) * 2;
            const float bb0 = bias[col], bb1 = bias[col + 1];
            float v0 = acc[mt][nt][0] + bb0, v1 = acc[mt][nt][1] + bb1;
            float v2 = acc[mt][nt][2] + bb0, v3 = acc[mt][nt][3] + bb1;
            if (relu) {
                v0 = fmaxf(v0, 0.f); v1 = fmaxf(v1, 0.f);
                v2 = fmaxf(v2, 0.f); v3 = fmaxf(v3, 0.f);
            }
            if (conv != 2) {
                *(float2*)(C + (size_t)r0 * ldc + col) = make_float2(v0, v1);
                *(float2*)(C + (size_t)(r0 + 8) * ldc + col) = make_float2(v2, v3);
            }
            if (conv) {
                __half* tb = (conv == 1) ? g_i0 : g_lb;
                *(__half2*)(tb + (size_t)r0 * ldc + col) =
                    __halves2half2(__float2half(v0), __float2half(v1));
                *(__half2*)(tb + (size_t)(r0 + 8) * ldc + col) =
                    __halves2half2(__float2half(v2), __float2half(v3));
            }
        }
    }
}

// ---------------- prep ----------------
__global__ void split_x2_kernel(const float* __restrict__ x) {
    size_t i = (size_t)blockIdx.x * blockDim.x + threadIdx.x;
    const size_t n = (size_t)NTOK * Hd;
    if (i >= n) return;
    float v = x[i];
    __half h0 = __float2half(v);
    g_xa0[i] = h0;
    g_xa1[i] = __float2half(v - __half2float(h0));
}

__global__ void transpose_split(const float* __restrict__ W, int R, int C,
                                int s0, int s1, int wf) {
    __half* T0 = bufselw(s0);
    __half* T1 = (s1 >= 0) ? bufselw(s1) : nullptr;
    float* TF = wf ? g_w2tf : nullptr;

    __shared__ float t[32][33];
    const int bx = blockIdx.x * 32, by = blockIdx.y * 32;
    const int tx = threadIdx.x, ty = threadIdx.y;
    #pragma unroll
    for (int i = 0; i < 4; i++)
        t[ty + i * 8][tx] = W[(size_t)(by + ty + i * 8) * C + bx + tx];
    __syncthreads();
    #pragma unroll
    for (int i = 0; i < 4; i++) {
        const int c = bx + ty + i * 8, r = by + tx;
        const float v = t[tx][ty + i * 8];
        const size_t o = (size_t)c * R + r;
        __half h0 = __float2half(v);
        T0[o] = h0;
        if (T1) T1[o] = __float2half(v - __half2float(h0));
        if (TF) TF[o] = v;
    }
}

// ---------------- reductions ----------------
template <int NT>
__device__ __forceinline__ float breduce(float v) {
    __shared__ float sh[NT];
    int tid = threadIdx.x;
    sh[tid] = v; __syncthreads();
    #pragma unroll
    for (int s = NT / 2; s > 0; s >>= 1) {
        if (tid < s) sh[tid] += sh[tid + s];
        __syncthreads();
    }
    float r = sh[0]; __syncthreads();
    return r;
}

__global__ void zero_usage_kernel() {
    int i = blockIdx.x * blockDim.x + threadIdx.x;
    if (i < Pd) g_usage[i] = 0.0f;
}

// ---------------- top-2: fp16 approx scan + exact fp32 recompute ------------
__global__ void __launch_bounds__(256)
topk_kernel(const float* __restrict__ pool, const float* __restrict__ temp_ptr,
            const float* __restrict__ b2)
{
    const int row = blockIdx.x, tid = threadIdx.x;
    const int wid = tid >> 5, lane = tid & 31;
    const __half* lrow = g_lb + (size_t)row * Pd;
    float t = temp_ptr[0];
    t = fminf(fmaxf(t, 0.1f), 5.0f);
    const float it = 1.0f / t;

    float v1 = -INFINITY, v2 = -INFINITY;
    for (int j = tid * 2; j < Pd; j += 512) {
        __half2 p2 = *(const __half2*)(lrow + j);
        float va = fminf(fmaxf(__low2float(p2) * it, -10.0f), 10.0f);
        float vb = fminf(fmaxf(__high2float(p2) * it, -10.0f), 10.0f);
        float hi = fmaxf(va, vb), lo = fminf(va, vb);
        if (hi > v1) { v2 = fmaxf(v1, lo); v1 = hi; }
        else v2 = fmaxf(v2, hi);
    }
    __shared__ float s1[256], s2[256];
    s1[tid] = v1; s2[tid] = v2; __syncthreads();
    for (int s = 128; s > 0; s >>= 1) {
        if (tid < s) {
            float a1 = s1[tid], a2 = s2[tid], b1v = s1[tid + s], b2v = s2[tid + s];
            s1[tid] = fmaxf(a1, b1v);
            s2[tid] = fmaxf(fminf(a1, b1v), fmaxf(a2, b2v));
        }
        __syncthreads();
    }
    const float thr = s2[0] - 0.02f * it;

    __shared__ int cands[64];
    __shared__ int ncand;
    if (tid == 0) ncand = 0;
    __syncthreads();
    for (int j = tid * 2; j < Pd; j += 512) {
        __half2 p2 = *(const __half2*)(lrow + j);
        float va = fminf(fmaxf(__low2float(p2) * it, -10.0f), 10.0f);
        float vb = fminf(fmaxf(__high2float(p2) * it, -10.0f), 10.0f);
        if (va >= thr) { int p = atomicAdd(&ncand, 1); if (p < 64) cands[p] = j; }
        if (vb >= thr) { int p = atomicAdd(&ncand, 1); if (p < 64) cands[p] = j + 1; }
    }
    __syncthreads();
    const int nc = min(ncand, 64);

    __shared__ float exv[64];
    const float* irow = g_inter + (size_t)row * Id;
    for (int base = 0; base < nc; base += 8) {
        const int q = base + wid;
        if (q < nc) {
            const int j = cands[q];
            const float* wr = g_w2tf + (size_t)j * Id;
            float s = 0.0f;
            for (int k = lane; k < Id; k += 32) s += irow[k] * wr[k];
            #pragma unroll
            for (int o = 16; o > 0; o >>= 1) s += __shfl_down_sync(0xffffffffu, s, o);
            if (lane == 0) exv[q] = fminf(fmaxf((s + b2[j]) / t, -10.0f), 10.0f);
        }
    }
    __syncthreads();

    __shared__ float sw0, sw1;
    __shared__ int sj0, sj1;
    if (tid == 0) {
        float bv1 = -INFINITY, bv2 = -INFINITY;
        int bi1 = 0x7fffffff, bi2 = 0x7fffffff;
        for (int q = 0; q < nc; q++) {
            float v = exv[q]; int j = cands[q];
            if (v > bv1 || (v == bv1 && j < bi1)) {
                bv2 = bv1; bi2 = bi1; bv1 = v; bi1 = j;
            } else if (v > bv2 || (v == bv2 && j < bi2)) {
                bv2 = v; bi2 = j;
            }
        }
        float e = expf(bv2 - bv1), se = 1.0f + e;
        sw0 = 1.0f / se; sw1 = e / se; sj0 = bi1; sj1 = bi2;
        atomicAdd(&g_usage[bi1], sw0);
        atomicAdd(&g_usage[bi2], sw1);
    }
    __syncthreads();

    const float w0 = sw0, w1 = sw1;
    float4 a = ((const float4*)(pool + (size_t)sj0 * Dd))[tid];
    float4 b = ((const float4*)(pool + (size_t)sj1 * Dd))[tid];
    float ov[4] = { w0 * a.x + w1 * b.x, w0 * a.y + w1 * b.y,
                    w0 * a.z + w1 * b.z, w0 * a.w + w1 * b.w };
    const size_t off = (size_t)row * (2 * Dd) + Dd + tid * 4;
    #pragma unroll
    for (int q = 0; q < 4; q++) {
        __half h0 = __float2half(ov[q]);
        g_ca0[off + q] = h0;
        g_ca1[off + q] = __float2half(ov[q] - __half2float(h0));
    }
}

// ---------------- layernorm -> combined[:, 0:D] splits ----------------
__global__ void __launch_bounds__(256)
ln_kernel(const float* __restrict__ gamma, const float* __restrict__ beta)
{
    const int row = blockIdx.x, tid = threadIdx.x;
    float4 v = ((const float4*)(g_proj + (size_t)row * Dd))[tid];
    float s = v.x + v.y + v.z + v.w;
    s = breduce<256>(s);
    const float mean = s * (1.0f / Dd);
    float d0 = v.x - mean, d1 = v.y - mean, d2 = v.z - mean, d3 = v.w - mean;
    float q = d0 * d0 + d1 * d1 + d2 * d2 + d3 * d3;
    q = breduce<256>(q);
    const float rs = rsqrtf(q * (1.0f / Dd) + 1e-5f);
    float4 g = ((const float4*)gamma)[tid], b = ((const float4*)beta)[tid];
    float ov[4] = { d0 * rs * g.x + b.x, d1 * rs * g.y + b.y,
                    d2 * rs * g.z + b.z, d3 * rs * g.w + b.w };
    const size_t off = (size_t)row * (2 * Dd) + tid * 4;
    #pragma unroll
    for (int k = 0; k < 4; k++) {
        __half h0 = __float2half(ov[k]);
        g_ca0[off + k] = h0;
        g_ca1[off + k] = __float2half(ov[k] - __half2float(h0));
    }
}

// ---------------- diversity loss ----------------
__global__ void __launch_bounds__(512)
loss_kernel(float* __restrict__ out, int do_write)
{
    const int tid = threadIdx.x;
    float s = 0.0f;
    for (int j = tid; j < Pd; j += 512) s += g_usage[j];
    s = breduce<512>(s);
    const float denom = s + 1e-8f, uni = 1.0f / Pd;
    float q = 0.0f;
    for (int j = tid; j < Pd; j += 512) {
        float d = g_usage[j] / denom - uni;
        q += d * d;
    }
    q = breduce<512>(q);
    if (tid == 0 && do_write) out[0] = (q / Pd) * 0.01f;
}

// ---------------- launch ----------------
extern "C" void kernel_launch(void* const* d_in, const int* in_sizes, int n_in,
                              void* d_out, int out_size)
{
    const int o = (n_in >= 14) ? 1 : 0;
    const float* x     = (const float*)d_in[0];
    const float* pool  = (const float*)d_in[1];
    const float* w1    = (const float*)d_in[2 + o];
    const float* b1    = (const float*)d_in[3 + o];
    const float* w2    = (const float*)d_in[4 + o];
    const float* b2    = (const float*)d_in[5 + o];
    const float* temp  = (const float*)d_in[6 + o];
    const float* wp    = (const float*)d_in[7 + o];
    const float* bp    = (const float*)d_in[8 + o];
    const float* gamma = (const float*)d_in[9 + o];
    const float* beta  = (const float*)d_in[10 + o];
    const float* wm    = (const float*)d_in[11 + o];
    const float* bm    = (const float*)d_in[12 + o];
    float* out = (float*)d_out;

    static int attr_done = 0;
    if (!attr_done) {
        cudaFuncSetAttribute(gemm_mma, cudaFuncAttributeMaxDynamicSharedMemorySize, SMEM_DYN);
        attr_done = 1;
    }

    split_x2_kernel<<<((size_t)NTOK * Hd + 255) / 256, 256>>>(x);
    transpose_split<<<dim3(Id / 32, Hd / 32), dim3(32, 8)>>>(w1, Hd, Id, 3, 4, 0);
    transpose_split<<<dim3(Pd / 32, Id / 32), dim3(32, 8)>>>(w2, Id, Pd, 7, -1, 1);
    transpose_split<<<dim3(Dd / 32, Hd / 32), dim3(32, 8)>>>(wp, Hd, Dd, 8, -1, 0);
    transpose_split<<<dim3(Dd / 32, (2 * Dd) / 32), dim3(32, 8)>>>(wm, 2 * Dd, Dd, 12, -1, 0);
    zero_usage_kernel<<<Pd / 256, 256>>>();

    // G1: inter = relu(x@w1+b1); 3-pass fp16; fp32 + fp16 copy
    gemm_mma<<<dim3(Id / 128, NTOK / 128), 256, SMEM_DYN>>>(
        0x100u, 0x343u, 3, Hd, b1, nullptr, 0, Id, 1, 1);

    // G2: logits = inter@w2+b2; 1-pass fp16 -> g_lb only
    gemm_mma<<<dim3(Pd / 128, NTOK / 128), 256, SMEM_DYN>>>(
        0x6u, 0x7u, 1, Id, b2, nullptr, 9, Pd, 0, 2);

    topk_kernel<<<NTOK, 256>>>(pool, temp, b2);

    // G3: proj = x@wp+bp; 2-pass fp16
    gemm_mma<<<dim3(Dd / 128, NTOK / 128), 256, SMEM_DYN>>>(
        0x10u, 0x88u, 2, Hd, bp, nullptr, 2, Dd, 0, 0);

    ln_kernel<<<NTOK, 256>>>(gamma, beta);

    // G4: out = combined@wm+bm; 2-pass fp16
    gemm_mma<<<dim3(Dd / 128, NTOK / 128), 256, SMEM_DYN>>>(
        0xBAu, 0xCCu, 2, 2 * Dd, bm, out, 9, Dd, 0, 0);

    const long long tsz = (long long)NTOK * Dd;
    loss_kernel<<<1, 512>>>(out + tsz, ((long long)out_size > tsz) ? 1 : 0);
}

// round 13
// speedup vs baseline: 1.0385x; 1.0385x over previous
#include <cuda_runtime.h>
#include <cuda_fp16.h>
#include <cstdint>
#include <cstddef>
#include <math.h>

#define NTOK 8192
#define Hd 2048
#define Id 1024
#define Pd 4096
#define Dd 1024

// ---------------- static device scratch (fp16 splits) ----------------
__device__ __half g_xa0[(size_t)NTOK * Hd];
__device__ __half g_xa1[(size_t)NTOK * Hd];
__device__ __half g_w1t0[(size_t)Id * Hd];
__device__ __half g_w1t1[(size_t)Id * Hd];
__device__ __half g_i0[(size_t)NTOK * Id];
__device__ __half g_w2t0[(size_t)Pd * Id];
__device__ float  g_w2tf[(size_t)Pd * Id];
__device__ __half g_wpt0[(size_t)Dd * Hd];
__device__ __half g_ca0[(size_t)NTOK * 2 * Dd];
__device__ __half g_ca1[(size_t)NTOK * 2 * Dd];
__device__ __half g_wmt0[(size_t)Dd * 2 * Dd];
__device__ __half g_lb[(size_t)NTOK * Pd];      // fp16 logits
__device__ float  g_inter[(size_t)NTOK * Id];
__device__ float  g_proj[(size_t)NTOK * Dd];
__device__ float  g_usage[Pd];

__device__ __forceinline__ __half* bufselw(int s) {
    switch (s) {
        case 0:  return g_xa0;  case 1:  return g_xa1;
        case 3:  return g_w1t0; case 4:  return g_w1t1;
        case 6:  return g_i0;   case 7:  return g_w2t0;
        case 8:  return g_wpt0;
        case 10: return g_ca0;  case 11: return g_ca1;
        default: return g_wmt0;
    }
}
__device__ __forceinline__ const __half* bufsel(int s) { return bufselw(s); }
__device__ __forceinline__ float* csel(int s, float* ext) {
    switch (s) {
        case 0: return g_inter;
        case 2: return g_proj;
        default: return ext;
    }
}

// ---------------- PTX helpers ----------------
__device__ __forceinline__ uint32_t smem_u32(const void* p) {
    uint32_t a;
    asm("{ .reg .u64 t; cvta.to.shared.u64 t, %1; cvt.u32.u64 %0, t; }" : "=r"(a) : "l"(p));
    return a;
}
#define CPA16(d, s) asm volatile("cp.async.cg.shared.global [%0], [%1], 16;" :: "r"(d), "l"(s) : "memory")
#define CPA_COMMIT() asm volatile("cp.async.commit_group;" ::: "memory")
#define CPA_WAIT2() asm volatile("cp.async.wait_group 2;" ::: "memory")
#define CPA_WAIT1() asm volatile("cp.async.wait_group 1;" ::: "memory")
#define CPA_WAIT0() asm volatile("cp.async.wait_group 0;" ::: "memory")

__device__ __forceinline__ void ldmx4(uint32_t* r, uint32_t addr) {
    asm volatile("ldmatrix.sync.aligned.m8n8.x4.shared.b16 {%0,%1,%2,%3}, [%4];"
                 : "=r"(r[0]), "=r"(r[1]), "=r"(r[2]), "=r"(r[3]) : "r"(addr));
}
__device__ __forceinline__ void mma16816(float* d, const uint32_t* a, const uint32_t* b) {
    asm volatile("mma.sync.aligned.m16n8k16.row.col.f32.f16.f16.f32 "
                 "{%0,%1,%2,%3}, {%4,%5,%6,%7}, {%8,%9}, {%0,%1,%2,%3};"
                 : "+f"(d[0]), "+f"(d[1]), "+f"(d[2]), "+f"(d[3])
                 : "r"(a[0]), "r"(a[1]), "r"(a[2]), "r"(a[3]), "r"(b[0]), "r"(b[1]));
}

// ---------------- HMMA GEMM: D[M,N] = sum_p A_p @ B_p^T + bias --------------
// Tile 128x128, BK=32, 3-stage static smem (48 KB), 2 CTAs/SM (R11 proven).
#define ST 3
#define STAGE_B 16384       // A 8KB + B 8KB

__device__ __forceinline__ uint32_t swzo(int row, int kcol) {
    return (uint32_t)(row * 64 + ((((kcol >> 3) ^ ((row >> 1) & 3)) << 4)) + ((kcol & 7) << 1));
}

__global__ void __launch_bounds__(256, 2)
gemm_mma(uint32_t aPack, uint32_t bPack, int npass, int K,
         const float* __restrict__ bias, float* Cext, int cselv, int ldc,
         int relu, int conv)   // conv: 0 none, 1 also fp16->g_i0, 2 fp16 ONLY ->g_lb
{
    __shared__ __align__(1024) char smem[ST * STAGE_B];
    const uint32_t sb = smem_u32(smem);
    const int tid = threadIdx.x, lane = tid & 31, wid = tid >> 5;
    const int wm = wid & 1, wn = wid >> 1;          // warp grid 2(M) x 4(N)
    const int bn = blockIdx.x, bm = blockIdx.y;
    float* C = csel(cselv, Cext);

    const int kcp = K >> 5;
    const int NCH = npass * kcp;

    float acc[4][4][4];
    #pragma unroll
    for (int i = 0; i < 4; i++)
        #pragma unroll
        for (int j = 0; j < 4; j++)
            #pragma unroll
            for (int q = 0; q < 4; q++) acc[i][j][q] = 0.0f;

    auto load_chunk = [&](int ch, int buf) {
        const int p = ch / kcp, kc = ch % kcp;
        const __half* A = bufsel((aPack >> (4 * p)) & 15) + (size_t)(bm * 128) * K + kc * 32;
        const __half* B = bufsel((bPack >> (4 * p)) & 15) + (size_t)(bn * 128) * K + kc * 32;
        const uint32_t ab = sb + buf * STAGE_B;
        const uint32_t bb = ab + 8192;
        #pragma unroll
        for (int i = 0; i < 2; i++) {
            const int g = tid + i * 256, r = g >> 2, c = g & 3;
            const uint32_t so = swzo(r, c * 8);
            CPA16(ab + so, A + (size_t)r * K + c * 8);
            CPA16(bb + so, B + (size_t)r * K + c * 8);
        }
        CPA_COMMIT();
    };

    load_chunk(0, 0);
    if (NCH > 1) load_chunk(1, 1);

    const int a_r = wm * 64 + (lane & 15);                      // + mt*16
    const int a_kc = (lane >> 4) * 8;                           // + ks*16
    const int b_r = wn * 32 + (lane & 7) + ((lane >> 4) << 3);  // + q*16
    const int b_kc = ((lane >> 3) & 1) * 8;                     // + ks*16

    for (int c = 0; c < NCH; c++) {
        if (c + 2 < NCH) { load_chunk(c + 2, (c + 2) % ST); CPA_WAIT2(); }
        else if (c + 1 < NCH) CPA_WAIT1();
        else CPA_WAIT0();
        __syncthreads();

        const uint32_t abase = sb + (c % ST) * STAGE_B;
        const uint32_t bbase = abase + 8192;
        #pragma unroll
        for (int ks = 0; ks < 2; ks++) {
            uint32_t af[4][4], bf[2][4];
            #pragma unroll
            for (int mt = 0; mt < 4; mt++)
                ldmx4(af[mt], abase + swzo(a_r + mt * 16, ks * 16 + a_kc));
            #pragma unroll
            for (int q = 0; q < 2; q++)
                ldmx4(bf[q], bbase + swzo(b_r + q * 16, ks * 16 + b_kc));
            #pragma unroll
            for (int mt = 0; mt < 4; mt++)
                #pragma unroll
                for (int nt = 0; nt < 4; nt++)
                    mma16816(acc[mt][nt], af[mt], &bf[nt >> 1][(nt & 1) * 2]);
        }
        __syncthreads();
    }

    #pragma unroll
    for (int mt = 0; mt < 4; mt++) {
        const int r0 = bm * 128 + wm * 64 + mt * 16 + (lane >> 2);
        #pragma unroll
        for (int nt = 0; nt < 4; nt++) {
            const int col = bn * 128 + wn * 32 + nt * 8 + (lane & 3) * 2;
            const float bb0 = bias[col], bb1 = bias[col + 1];
            float v0 = acc[mt][nt][0] + bb0, v1 = acc[mt][nt][1] + bb1;
            float v2 = acc[mt][nt][2] + bb0, v3 = acc[mt][nt][3] + bb1;
            if (relu) {
                v0 = fmaxf(v0, 0.f); v1 = fmaxf(v1, 0.f);
                v2 = fmaxf(v2, 0.f); v3 = fmaxf(v3, 0.f);
            }
            if (conv != 2) {
                *(float2*)(C + (size_t)r0 * ldc + col) = make_float2(v0, v1);
                *(float2*)(C + (size_t)(r0 + 8) * ldc + col) = make_float2(v2, v3);
            }
            if (conv) {
                __half* tb = (conv == 1) ? g_i0 : g_lb;
                *(__half2*)(tb + (size_t)r0 * ldc + col) =
                    __halves2half2(__float2half(v0), __float2half(v1));
                *(__half2*)(tb + (size_t)(r0 + 8) * ldc + col) =
                    __halves2half2(__float2half(v2), __float2half(v3));
            }
        }
    }
}

// ---------------- prep ----------------
__global__ void split_x2_kernel(const float* __restrict__ x) {
    size_t i = (size_t)blockIdx.x * blockDim.x + threadIdx.x;
    const size_t n = (size_t)NTOK * Hd;
    if (i >= n) return;
    float v = x[i];
    __half h0 = __float2half(v);
    g_xa0[i] = h0;
    g_xa1[i] = __float2half(v - __half2float(h0));
}

__global__ void transpose_split(const float* __restrict__ W, int R, int C,
                                int s0, int s1, int wf) {
    __half* T0 = bufselw(s0);
    __half* T1 = (s1 >= 0) ? bufselw(s1) : nullptr;
    float* TF = wf ? g_w2tf : nullptr;

    __shared__ float t[32][33];
    const int bx = blockIdx.x * 32, by = blockIdx.y * 32;
    const int tx = threadIdx.x, ty = threadIdx.y;
    #pragma unroll
    for (int i = 0; i < 4; i++)
        t[ty + i * 8][tx] = W[(size_t)(by + ty + i * 8) * C + bx + tx];
    __syncthreads();
    #pragma unroll
    for (int i = 0; i < 4; i++) {
        const int c = bx + ty + i * 8, r = by + tx;
        const float v = t[tx][ty + i * 8];
        const size_t o = (size_t)c * R + r;
        __half h0 = __float2half(v);
        T0[o] = h0;
        if (T1) T1[o] = __float2half(v - __half2float(h0));
        if (TF) TF[o] = v;
    }
}

// ---------------- reductions ----------------
template <int NT>
__device__ __forceinline__ float breduce(float v) {
    __shared__ float sh[NT];
    int tid = threadIdx.x;
    sh[tid] = v; __syncthreads();
    #pragma unroll
    for (int s = NT / 2; s > 0; s >>= 1) {
        if (tid < s) sh[tid] += sh[tid + s];
        __syncthreads();
    }
    float r = sh[0]; __syncthreads();
    return r;
}

__global__ void zero_usage_kernel() {
    int i = blockIdx.x * blockDim.x + threadIdx.x;
    if (i < Pd) g_usage[i] = 0.0f;
}

// ---------------- top-2: fp16 approx scan + exact fp32 recompute ------------
__global__ void __launch_bounds__(256)
topk_kernel(const float* __restrict__ pool, const float* __restrict__ temp_ptr,
            const float* __restrict__ b2)
{
    const int row = blockIdx.x, tid = threadIdx.x;
    const int wid = tid >> 5, lane = tid & 31;
    const __half* lrow = g_lb + (size_t)row * Pd;
    float t = temp_ptr[0];
    t = fminf(fmaxf(t, 0.1f), 5.0f);
    const float it = 1.0f / t;

    float v1 = -INFINITY, v2 = -INFINITY;
    for (int j = tid * 2; j < Pd; j += 512) {
        __half2 p2 = *(const __half2*)(lrow + j);
        float va = fminf(fmaxf(__low2float(p2) * it, -10.0f), 10.0f);
        float vb = fminf(fmaxf(__high2float(p2) * it, -10.0f), 10.0f);
        float hi = fmaxf(va, vb), lo = fminf(va, vb);
        if (hi > v1) { v2 = fmaxf(v1, lo); v1 = hi; }
        else v2 = fmaxf(v2, hi);
    }
    __shared__ float s1[256], s2[256];
    s1[tid] = v1; s2[tid] = v2; __syncthreads();
    for (int s = 128; s > 0; s >>= 1) {
        if (tid < s) {
            float a1 = s1[tid], a2 = s2[tid], b1v = s1[tid + s], b2v = s2[tid + s];
            s1[tid] = fmaxf(a1, b1v);
            s2[tid] = fmaxf(fminf(a1, b1v), fmaxf(a2, b2v));
        }
        __syncthreads();
    }
    const float thr = s2[0] - 0.02f * it;

    __shared__ int cands[64];
    __shared__ int ncand;
    if (tid == 0) ncand = 0;
    __syncthreads();
    for (int j = tid * 2; j < Pd; j += 512) {
        __half2 p2 = *(const __half2*)(lrow + j);
        float va = fminf(fmaxf(__low2float(p2) * it, -10.0f), 10.0f);
        float vb = fminf(fmaxf(__high2float(p2) * it, -10.0f), 10.0f);
        if (va >= thr) { int p = atomicAdd(&ncand, 1); if (p < 64) cands[p] = j; }
        if (vb >= thr) { int p = atomicAdd(&ncand, 1); if (p < 64) cands[p] = j + 1; }
    }
    __syncthreads();
    const int nc = min(ncand, 64);

    __shared__ float exv[64];
    const float* irow = g_inter + (size_t)row * Id;
    for (int base = 0; base < nc; base += 8) {
        const int q = base + wid;
        if (q < nc) {
            const int j = cands[q];
            const float* wr = g_w2tf + (size_t)j * Id;
            float s = 0.0f;
            for (int k = lane; k < Id; k += 32) s += irow[k] * wr[k];
            #pragma unroll
            for (int o = 16; o > 0; o >>= 1) s += __shfl_down_sync(0xffffffffu, s, o);
            if (lane == 0) exv[q] = fminf(fmaxf((s + b2[j]) / t, -10.0f), 10.0f);
        }
    }
    __syncthreads();

    __shared__ float sw0, sw1;
    __shared__ int sj0, sj1;
    if (tid == 0) {
        float bv1 = -INFINITY, bv2 = -INFINITY;
        int bi1 = 0x7fffffff, bi2 = 0x7fffffff;
        for (int q = 0; q < nc; q++) {
            float v = exv[q]; int j = cands[q];
            if (v > bv1 || (v == bv1 && j < bi1)) {
                bv2 = bv1; bi2 = bi1; bv1 = v; bi1 = j;
            } else if (v > bv2 || (v == bv2 && j < bi2)) {
                bv2 = v; bi2 = j;
            }
        }
        float e = expf(bv2 - bv1), se = 1.0f + e;
        sw0 = 1.0f / se; sw1 = e / se; sj0 = bi1; sj1 = bi2;
        atomicAdd(&g_usage[bi1], sw0);
        atomicAdd(&g_usage[bi2], sw1);
    }
    __syncthreads();

    const float w0 = sw0, w1 = sw1;
    float4 a = ((const float4*)(pool + (size_t)sj0 * Dd))[tid];
    float4 b = ((const float4*)(pool + (size_t)sj1 * Dd))[tid];
    float ov[4] = { w0 * a.x + w1 * b.x, w0 * a.y + w1 * b.y,
                    w0 * a.z + w1 * b.z, w0 * a.w + w1 * b.w };
    const size_t off = (size_t)row * (2 * Dd) + Dd + tid * 4;
    #pragma unroll
    for (int q = 0; q < 4; q++) {
        __half h0 = __float2half(ov[q]);
        g_ca0[off + q] = h0;
        g_ca1[off + q] = __float2half(ov[q] - __half2float(h0));
    }
}

// ---------------- layernorm -> combined[:, 0:D] splits ----------------
__global__ void __launch_bounds__(256)
ln_kernel(const float* __restrict__ gamma, const float* __restrict__ beta)
{
    const int row = blockIdx.x, tid = threadIdx.x;
    float4 v = ((const float4*)(g_proj + (size_t)row * Dd))[tid];
    float s = v.x + v.y + v.z + v.w;
    s = breduce<256>(s);
    const float mean = s * (1.0f / Dd);
    float d0 = v.x - mean, d1 = v.y - mean, d2 = v.z - mean, d3 = v.w - mean;
    float q = d0 * d0 + d1 * d1 + d2 * d2 + d3 * d3;
    q = breduce<256>(q);
    const float rs = rsqrtf(q * (1.0f / Dd) + 1e-5f);
    float4 g = ((const float4*)gamma)[tid], b = ((const float4*)beta)[tid];
    float ov[4] = { d0 * rs * g.x + b.x, d1 * rs * g.y + b.y,
                    d2 * rs * g.z + b.z, d3 * rs * g.w + b.w };
    const size_t off = (size_t)row * (2 * Dd) + tid * 4;
    #pragma unroll
    for (int k = 0; k < 4; k++) {
        __half h0 = __float2half(ov[k]);
        g_ca0[off + k] = h0;
        g_ca1[off + k] = __float2half(ov[k] - __half2float(h0));
    }
}

// ---------------- diversity loss ----------------
__global__ void __launch_bounds__(512)
loss_kernel(float* __restrict__ out, int do_write)
{
    const int tid = threadIdx.x;
    float s = 0.0f;
    for (int j = tid; j < Pd; j += 512) s += g_usage[j];
    s = breduce<512>(s);
    const float denom = s + 1e-8f, uni = 1.0f / Pd;
    float q = 0.0f;
    for (int j = tid; j < Pd; j += 512) {
        float d = g_usage[j] / denom - uni;
        q += d * d;
    }
    q = breduce<512>(q);
    if (tid == 0 && do_write) out[0] = (q / Pd) * 0.01f;
}

// ---------------- launch (fork-join streams, graph-capturable) --------------
extern "C" void kernel_launch(void* const* d_in, const int* in_sizes, int n_in,
                              void* d_out, int out_size)
{
    const int o = (n_in >= 14) ? 1 : 0;
    const float* x     = (const float*)d_in[0];
    const float* pool  = (const float*)d_in[1];
    const float* w1    = (const float*)d_in[2 + o];
    const float* b1    = (const float*)d_in[3 + o];
    const float* w2    = (const float*)d_in[4 + o];
    const float* b2    = (const float*)d_in[5 + o];
    const float* temp  = (const float*)d_in[6 + o];
    const float* wp    = (const float*)d_in[7 + o];
    const float* bp    = (const float*)d_in[8 + o];
    const float* gamma = (const float*)d_in[9 + o];
    const float* beta  = (const float*)d_in[10 + o];
    const float* wm    = (const float*)d_in[11 + o];
    const float* bm    = (const float*)d_in[12 + o];
    float* out = (float*)d_out;

    // one-time resources (created on the uncaptured correctness call)
    static cudaStream_t sB = nullptr;
    static cudaEvent_t evFork = nullptr, evJoin = nullptr;
    if (!sB) {
        cudaStreamCreateWithFlags(&sB, cudaStreamNonBlocking);
        cudaEventCreateWithFlags(&evFork, cudaEventDisableTiming);
        cudaEventCreateWithFlags(&evJoin, cudaEventDisableTiming);
    }

    // ---- prep (default stream) ----
    split_x2_kernel<<<((size_t)NTOK * Hd + 255) / 256, 256>>>(x);
    transpose_split<<<dim3(Id / 32, Hd / 32), dim3(32, 8)>>>(w1, Hd, Id, 3, 4, 0);
    transpose_split<<<dim3(Pd / 32, Id / 32), dim3(32, 8)>>>(w2, Id, Pd, 7, -1, 1);
    transpose_split<<<dim3(Dd / 32, Hd / 32), dim3(32, 8)>>>(wp, Hd, Dd, 8, -1, 0);
    transpose_split<<<dim3(Dd / 32, (2 * Dd) / 32), dim3(32, 8)>>>(wm, 2 * Dd, Dd, 12, -1, 0);
    zero_usage_kernel<<<Pd / 256, 256>>>();

    // ---- fork: side chain (G3 -> ln) runs concurrent with G1->G2->topk ----
    cudaEventRecord(evFork, 0);
    cudaStreamWaitEvent(sB, evFork, 0);

    // side stream: G3 proj = x@wp+bp (2-pass fp16), then layernorm
    gemm_mma<<<dim3(Dd / 128, NTOK / 128), 256, 0, sB>>>(
        0x10u, 0x88u, 2, Hd, bp, nullptr, 2, Dd, 0, 0);
    ln_kernel<<<NTOK, 256, 0, sB>>>(gamma, beta);
    cudaEventRecord(evJoin, sB);

    // main stream: G1 inter = relu(x@w1+b1), 3-pass; fp32 + fp16 copy
    gemm_mma<<<dim3(Id / 128, NTOK / 128), 256>>>(
        0x100u, 0x343u, 3, Hd, b1, nullptr, 0, Id, 1, 1);
    // G2: logits = inter@w2+b2; 1-pass fp16 -> g_lb only
    gemm_mma<<<dim3(Pd / 128, NTOK / 128), 256>>>(
        0x6u, 0x7u, 1, Id, b2, nullptr, 9, Pd, 0, 2);
    // top-2 + softmax + usage + pool gather
    topk_kernel<<<NTOK, 256>>>(pool, temp, b2);
    // loss (reads usage only; writes out[tsz], disjoint from G4's region)
    const long long tsz = (long long)NTOK * Dd;
    loss_kernel<<<1, 512>>>(out + tsz, ((long long)out_size > tsz) ? 1 : 0);

    // ---- join: G4 needs ln (side) + topk (main) ----
    cudaStreamWaitEvent(0, evJoin, 0);

    // G4: out = combined@wm+bm; 2-pass fp16
    gemm_mma<<<dim3(Dd / 128, NTOK / 128), 256>>>(
        0xBAu, 0xCCu, 2, 2 * Dd, bm, out, 9, Dd, 0, 0);
}

// round 14
// speedup vs baseline: 1.0837x; 1.0435x over previous
#include <cuda_runtime.h>
#include <cuda_fp16.h>
#include <cstdint>
#include <cstddef>
#include <math.h>

#define NTOK 8192
#define Hd 2048
#define Id 1024
#define Pd 4096
#define Dd 1024

// ---------------- static device scratch (fp16 splits) ----------------
__device__ __half g_xa0[(size_t)NTOK * Hd];
__device__ __half g_xa1[(size_t)NTOK * Hd];
__device__ __half g_w1t0[(size_t)Id * Hd];
__device__ __half g_w1t1[(size_t)Id * Hd];
__device__ __half g_i0[(size_t)NTOK * Id];
__device__ __half g_w2t0[(size_t)Pd * Id];
__device__ float  g_w2tf[(size_t)Pd * Id];
__device__ __half g_wpt0[(size_t)Dd * Hd];
__device__ __half g_ca0[(size_t)NTOK * 2 * Dd];
__device__ __half g_ca1[(size_t)NTOK * 2 * Dd];
__device__ __half g_wmt0[(size_t)Dd * 2 * Dd];
__device__ __half g_lb[(size_t)NTOK * Pd];      // fp16 logits
__device__ float  g_inter[(size_t)NTOK * Id];
__device__ float  g_proj[(size_t)NTOK * Dd];
__device__ float  g_usage[Pd];

__device__ __forceinline__ __half* bufselw(int s) {
    switch (s) {
        case 0:  return g_xa0;  case 1:  return g_xa1;
        case 3:  return g_w1t0; case 4:  return g_w1t1;
        case 6:  return g_i0;   case 7:  return g_w2t0;
        case 8:  return g_wpt0;
        case 10: return g_ca0;  case 11: return g_ca1;
        default: return g_wmt0;
    }
}
__device__ __forceinline__ const __half* bufsel(int s) { return bufselw(s); }
__device__ __forceinline__ float* csel(int s, float* ext) {
    switch (s) {
        case 0: return g_inter;
        case 2: return g_proj;
        default: return ext;
    }
}

// ---------------- PTX helpers ----------------
__device__ __forceinline__ uint32_t smem_u32(const void* p) {
    uint32_t a;
    asm("{ .reg .u64 t; cvta.to.shared.u64 t, %1; cvt.u32.u64 %0, t; }" : "=r"(a) : "l"(p));
    return a;
}
#define CPA16(d, s) asm volatile("cp.async.cg.shared.global [%0], [%1], 16;" :: "r"(d), "l"(s) : "memory")
#define CPA_COMMIT() asm volatile("cp.async.commit_group;" ::: "memory")
#define CPA_WAIT2() asm volatile("cp.async.wait_group 2;" ::: "memory")
#define CPA_WAIT1() asm volatile("cp.async.wait_group 1;" ::: "memory")
#define CPA_WAIT0() asm volatile("cp.async.wait_group 0;" ::: "memory")

__device__ __forceinline__ void ldmx4(uint32_t* r, uint32_t addr) {
    asm volatile("ldmatrix.sync.aligned.m8n8.x4.shared.b16 {%0,%1,%2,%3}, [%4];"
                 : "=r"(r[0]), "=r"(r[1]), "=r"(r[2]), "=r"(r[3]) : "r"(addr));
}
__device__ __forceinline__ void mma16816(float* d, const uint32_t* a, const uint32_t* b) {
    asm volatile("mma.sync.aligned.m16n8k16.row.col.f32.f16.f16.f32 "
                 "{%0,%1,%2,%3}, {%4,%5,%6,%7}, {%8,%9}, {%0,%1,%2,%3};"
                 : "+f"(d[0]), "+f"(d[1]), "+f"(d[2]), "+f"(d[3])
                 : "r"(a[0]), "r"(a[1]), "r"(a[2]), "r"(a[3]), "r"(b[0]), "r"(b[1]));
}

// ---------------- HMMA GEMM (R11/R13 proven config) ----------------
#define ST 3
#define STAGE_B 16384       // A 8KB + B 8KB

__device__ __forceinline__ uint32_t swzo(int row, int kcol) {
    return (uint32_t)(row * 64 + ((((kcol >> 3) ^ ((row >> 1) & 3)) << 4)) + ((kcol & 7) << 1));
}

__global__ void __launch_bounds__(256, 2)
gemm_mma(uint32_t aPack, uint32_t bPack, int npass, int K,
         const float* __restrict__ bias, float* Cext, int cselv, int ldc,
         int relu, int conv)   // conv: 0 none, 1 also fp16->g_i0, 2 fp16 ONLY ->g_lb
{
    __shared__ __align__(1024) char smem[ST * STAGE_B];
    const uint32_t sb = smem_u32(smem);
    const int tid = threadIdx.x, lane = tid & 31, wid = tid >> 5;
    const int wm = wid & 1, wn = wid >> 1;
    const int bn = blockIdx.x, bm = blockIdx.y;
    float* C = csel(cselv, Cext);

    const int kcp = K >> 5;
    const int NCH = npass * kcp;

    float acc[4][4][4];
    #pragma unroll
    for (int i = 0; i < 4; i++)
        #pragma unroll
        for (int j = 0; j < 4; j++)
            #pragma unroll
            for (int q = 0; q < 4; q++) acc[i][j][q] = 0.0f;

    auto load_chunk = [&](int ch, int buf) {
        const int p = ch / kcp, kc = ch % kcp;
        const __half* A = bufsel((aPack >> (4 * p)) & 15) + (size_t)(bm * 128) * K + kc * 32;
        const __half* B = bufsel((bPack >> (4 * p)) & 15) + (size_t)(bn * 128) * K + kc * 32;
        const uint32_t ab = sb + buf * STAGE_B;
        const uint32_t bb = ab + 8192;
        #pragma unroll
        for (int i = 0; i < 2; i++) {
            const int g = tid + i * 256, r = g >> 2, c = g & 3;
            const uint32_t so = swzo(r, c * 8);
            CPA16(ab + so, A + (size_t)r * K + c * 8);
            CPA16(bb + so, B + (size_t)r * K + c * 8);
        }
        CPA_COMMIT();
    };

    load_chunk(0, 0);
    if (NCH > 1) load_chunk(1, 1);

    const int a_r = wm * 64 + (lane & 15);
    const int a_kc = (lane >> 4) * 8;
    const int b_r = wn * 32 + (lane & 7) + ((lane >> 4) << 3);
    const int b_kc = ((lane >> 3) & 1) * 8;

    for (int c = 0; c < NCH; c++) {
        if (c + 2 < NCH) { load_chunk(c + 2, (c + 2) % ST); CPA_WAIT2(); }
        else if (c + 1 < NCH) CPA_WAIT1();
        else CPA_WAIT0();
        __syncthreads();

        const uint32_t abase = sb + (c % ST) * STAGE_B;
        const uint32_t bbase = abase + 8192;
        #pragma unroll
        for (int ks = 0; ks < 2; ks++) {
            uint32_t af[4][4], bf[2][4];
            #pragma unroll
            for (int mt = 0; mt < 4; mt++)
                ldmx4(af[mt], abase + swzo(a_r + mt * 16, ks * 16 + a_kc));
            #pragma unroll
            for (int q = 0; q < 2; q++)
                ldmx4(bf[q], bbase + swzo(b_r + q * 16, ks * 16 + b_kc));
            #pragma unroll
            for (int mt = 0; mt < 4; mt++)
                #pragma unroll
                for (int nt = 0; nt < 4; nt++)
                    mma16816(acc[mt][nt], af[mt], &bf[nt >> 1][(nt & 1) * 2]);
        }
        __syncthreads();
    }

    #pragma unroll
    for (int mt = 0; mt < 4; mt++) {
        const int r0 = bm * 128 + wm * 64 + mt * 16 + (lane >> 2);
        #pragma unroll
        for (int nt = 0; nt < 4; nt++) {
            const int col = bn * 128 + wn * 32 + nt * 8 + (lane & 3) * 2;
            const float bb0 = bias[col], bb1 = bias[col + 1];
            float v0 = acc[mt][nt][0] + bb0, v1 = acc[mt][nt][1] + bb1;
            float v2 = acc[mt][nt][2] + bb0, v3 = acc[mt][nt][3] + bb1;
            if (relu) {
                v0 = fmaxf(v0, 0.f); v1 = fmaxf(v1, 0.f);
                v2 = fmaxf(v2, 0.f); v3 = fmaxf(v3, 0.f);
            }
            if (conv != 2) {
                *(float2*)(C + (size_t)r0 * ldc + col) = make_float2(v0, v1);
                *(float2*)(C + (size_t)(r0 + 8) * ldc + col) = make_float2(v2, v3);
            }
            if (conv) {
                __half* tb = (conv == 1) ? g_i0 : g_lb;
                *(__half2*)(tb + (size_t)r0 * ldc + col) =
                    __halves2half2(__float2half(v0), __float2half(v1));
                *(__half2*)(tb + (size_t)(r0 + 8) * ldc + col) =
                    __halves2half2(__float2half(v2), __float2half(v3));
            }
        }
    }
}

// ---------------- prep ----------------
__global__ void split_x2_kernel(const float* __restrict__ x) {
    size_t i = (size_t)blockIdx.x * blockDim.x + threadIdx.x;
    const size_t n = (size_t)NTOK * Hd;
    if (i >= n) return;
    float v = x[i];
    __half h0 = __float2half(v);
    g_xa0[i] = h0;
    g_xa1[i] = __float2half(v - __half2float(h0));
}

__global__ void transpose_split(const float* __restrict__ W, int R, int C,
                                int s0, int s1, int wf) {
    __half* T0 = bufselw(s0);
    __half* T1 = (s1 >= 0) ? bufselw(s1) : nullptr;
    float* TF = wf ? g_w2tf : nullptr;

    __shared__ float t[32][33];
    const int bx = blockIdx.x * 32, by = blockIdx.y * 32;
    const int tx = threadIdx.x, ty = threadIdx.y;
    #pragma unroll
    for (int i = 0; i < 4; i++)
        t[ty + i * 8][tx] = W[(size_t)(by + ty + i * 8) * C + bx + tx];
    __syncthreads();
    #pragma unroll
    for (int i = 0; i < 4; i++) {
        const int c = bx + ty + i * 8, r = by + tx;
        const float v = t[tx][ty + i * 8];
        const size_t o = (size_t)c * R + r;
        __half h0 = __float2half(v);
        T0[o] = h0;
        if (T1) T1[o] = __float2half(v - __half2float(h0));
        if (TF) TF[o] = v;
    }
}

// ---------------- reductions ----------------
template <int NT>
__device__ __forceinline__ float breduce(float v) {
    __shared__ float sh[NT];
    int tid = threadIdx.x;
    sh[tid] = v; __syncthreads();
    #pragma unroll
    for (int s = NT / 2; s > 0; s >>= 1) {
        if (tid < s) sh[tid] += sh[tid + s];
        __syncthreads();
    }
    float r = sh[0]; __syncthreads();
    return r;
}

__global__ void zero_usage_kernel() {
    int i = blockIdx.x * blockDim.x + threadIdx.x;
    if (i < Pd) g_usage[i] = 0.0f;
}

// ---------------- top-2: SINGLE-sweep (register-cached) + exact recompute ----
__global__ void __launch_bounds__(256)
topk_kernel(const float* __restrict__ pool, const float* __restrict__ temp_ptr,
            const float* __restrict__ b2)
{
    const int row = blockIdx.x, tid = threadIdx.x;
    const int wid = tid >> 5, lane = tid & 31;
    const __half* lrow = g_lb + (size_t)row * Pd;
    float t = temp_ptr[0];
    t = fminf(fmaxf(t, 0.1f), 5.0f);
    const float it = 1.0f / t;

    // one global sweep: cache all 16 clamped values per thread in registers
    float cache[16];
    float v1 = -INFINITY, v2 = -INFINITY;
    #pragma unroll
    for (int itr = 0; itr < 8; itr++) {
        const int j = tid * 2 + itr * 512;
        __half2 p2 = *(const __half2*)(lrow + j);
        float va = fminf(fmaxf(__low2float(p2) * it, -10.0f), 10.0f);
        float vb = fminf(fmaxf(__high2float(p2) * it, -10.0f), 10.0f);
        cache[itr * 2] = va; cache[itr * 2 + 1] = vb;
        float hi = fmaxf(va, vb), lo = fminf(va, vb);
        if (hi > v1) { v2 = fmaxf(v1, lo); v1 = hi; }
        else v2 = fmaxf(v2, hi);
    }
    __shared__ float s1[256], s2[256];
    s1[tid] = v1; s2[tid] = v2; __syncthreads();
    for (int s = 128; s > 0; s >>= 1) {
        if (tid < s) {
            float a1 = s1[tid], a2 = s2[tid], b1v = s1[tid + s], b2v = s2[tid + s];
            s1[tid] = fmaxf(a1, b1v);
            s2[tid] = fmaxf(fminf(a1, b1v), fmaxf(a2, b2v));
        }
        __syncthreads();
    }
    const float thr = s2[0] - 0.02f * it;

    // candidate scan from registers — no second global read
    __shared__ int cands[64];
    __shared__ int ncand;
    if (tid == 0) ncand = 0;
    __syncthreads();
    #pragma unroll
    for (int itr = 0; itr < 8; itr++) {
        const int j = tid * 2 + itr * 512;
        if (cache[itr * 2] >= thr)     { int p = atomicAdd(&ncand, 1); if (p < 64) cands[p] = j; }
        if (cache[itr * 2 + 1] >= thr) { int p = atomicAdd(&ncand, 1); if (p < 64) cands[p] = j + 1; }
    }
    __syncthreads();
    const int nc = min(ncand, 64);

    __shared__ float exv[64];
    const float* irow = g_inter + (size_t)row * Id;
    for (int base = 0; base < nc; base += 8) {
        const int q = base + wid;
        if (q < nc) {
            const int j = cands[q];
            const float* wr = g_w2tf + (size_t)j * Id;
            float s = 0.0f;
            for (int k = lane; k < Id; k += 32) s += irow[k] * wr[k];
            #pragma unroll
            for (int o = 16; o > 0; o >>= 1) s += __shfl_down_sync(0xffffffffu, s, o);
            if (lane == 0) exv[q] = fminf(fmaxf((s + b2[j]) / t, -10.0f), 10.0f);
        }
    }
    __syncthreads();

    __shared__ float sw0, sw1;
    __shared__ int sj0, sj1;
    if (tid == 0) {
        float bv1 = -INFINITY, bv2 = -INFINITY;
        int bi1 = 0x7fffffff, bi2 = 0x7fffffff;
        for (int q = 0; q < nc; q++) {
            float v = exv[q]; int j = cands[q];
            if (v > bv1 || (v == bv1 && j < bi1)) {
                bv2 = bv1; bi2 = bi1; bv1 = v; bi1 = j;
            } else if (v > bv2 || (v == bv2 && j < bi2)) {
                bv2 = v; bi2 = j;
            }
        }
        float e = expf(bv2 - bv1), se = 1.0f + e;
        sw0 = 1.0f / se; sw1 = e / se; sj0 = bi1; sj1 = bi2;
        atomicAdd(&g_usage[bi1], sw0);
        atomicAdd(&g_usage[bi2], sw1);
    }
    __syncthreads();

    const float w0 = sw0, w1 = sw1;
    float4 a = ((const float4*)(pool + (size_t)sj0 * Dd))[tid];
    float4 b = ((const float4*)(pool + (size_t)sj1 * Dd))[tid];
    float ov[4] = { w0 * a.x + w1 * b.x, w0 * a.y + w1 * b.y,
                    w0 * a.z + w1 * b.z, w0 * a.w + w1 * b.w };
    const size_t off = (size_t)row * (2 * Dd) + Dd + tid * 4;
    #pragma unroll
    for (int q = 0; q < 4; q++) {
        __half h0 = __float2half(ov[q]);
        g_ca0[off + q] = h0;
        g_ca1[off + q] = __float2half(ov[q] - __half2float(h0));
    }
}

// ---------------- layernorm -> combined[:, 0:D] splits ----------------
__global__ void __launch_bounds__(256)
ln_kernel(const float* __restrict__ gamma, const float* __restrict__ beta)
{
    const int row = blockIdx.x, tid = threadIdx.x;
    float4 v = ((const float4*)(g_proj + (size_t)row * Dd))[tid];
    float s = v.x + v.y + v.z + v.w;
    s = breduce<256>(s);
    const float mean = s * (1.0f / Dd);
    float d0 = v.x - mean, d1 = v.y - mean, d2 = v.z - mean, d3 = v.w - mean;
    float q = d0 * d0 + d1 * d1 + d2 * d2 + d3 * d3;
    q = breduce<256>(q);
    const float rs = rsqrtf(q * (1.0f / Dd) + 1e-5f);
    float4 g = ((const float4*)gamma)[tid], b = ((const float4*)beta)[tid];
    float ov[4] = { d0 * rs * g.x + b.x, d1 * rs * g.y + b.y,
                    d2 * rs * g.z + b.z, d3 * rs * g.w + b.w };
    const size_t off = (size_t)row * (2 * Dd) + tid * 4;
    #pragma unroll
    for (int k = 0; k < 4; k++) {
        __half h0 = __float2half(ov[k]);
        g_ca0[off + k] = h0;
        g_ca1[off + k] = __float2half(ov[k] - __half2float(h0));
    }
}

// ---------------- diversity loss ----------------
__global__ void __launch_bounds__(512)
loss_kernel(float* __restrict__ out, int do_write)
{
    const int tid = threadIdx.x;
    float s = 0.0f;
    for (int j = tid; j < Pd; j += 512) s += g_usage[j];
    s = breduce<512>(s);
    const float denom = s + 1e-8f, uni = 1.0f / Pd;
    float q = 0.0f;
    for (int j = tid; j < Pd; j += 512) {
        float d = g_usage[j] / denom - uni;
        q += d * d;
    }
    q = breduce<512>(q);
    if (tid == 0 && do_write) out[0] = (q / Pd) * 0.01f;
}

// ---------------- launch (fork-join streams, graph-capturable) --------------
extern "C" void kernel_launch(void* const* d_in, const int* in_sizes, int n_in,
                              void* d_out, int out_size)
{
    const int o = (n_in >= 14) ? 1 : 0;
    const float* x     = (const float*)d_in[0];
    const float* pool  = (const float*)d_in[1];
    const float* w1    = (const float*)d_in[2 + o];
    const float* b1    = (const float*)d_in[3 + o];
    const float* w2    = (const float*)d_in[4 + o];
    const float* b2    = (const float*)d_in[5 + o];
    const float* temp  = (const float*)d_in[6 + o];
    const float* wp    = (const float*)d_in[7 + o];
    const float* bp    = (const float*)d_in[8 + o];
    const float* gamma = (const float*)d_in[9 + o];
    const float* beta  = (const float*)d_in[10 + o];
    const float* wm    = (const float*)d_in[11 + o];
    const float* bm    = (const float*)d_in[12 + o];
    float* out = (float*)d_out;

    static cudaStream_t sB = nullptr;
    static cudaEvent_t evFork = nullptr, evJoin = nullptr;
    if (!sB) {
        cudaStreamCreateWithFlags(&sB, cudaStreamNonBlocking);
        cudaEventCreateWithFlags(&evFork, cudaEventDisableTiming);
        cudaEventCreateWithFlags(&evJoin, cudaEventDisableTiming);
    }

    // split first (both chains need xa0/xa1), then fork
    split_x2_kernel<<<((size_t)NTOK * Hd + 255) / 256, 256>>>(x);
    cudaEventRecord(evFork, 0);
    cudaStreamWaitEvent(sB, evFork, 0);

    // ---- side stream: wp transpose -> G3 -> ln -> wm transpose ----
    transpose_split<<<dim3(Dd / 32, Hd / 32), dim3(32, 8), 0, sB>>>(wp, Hd, Dd, 8, -1, 0);
    gemm_mma<<<dim3(Dd / 128, NTOK / 128), 256, 0, sB>>>(
        0x10u, 0x88u, 2, Hd, bp, nullptr, 2, Dd, 0, 0);
    ln_kernel<<<NTOK, 256, 0, sB>>>(gamma, beta);
    transpose_split<<<dim3(Dd / 32, (2 * Dd) / 32), dim3(32, 8), 0, sB>>>(wm, 2 * Dd, Dd, 12, -1, 0);
    cudaEventRecord(evJoin, sB);

    // ---- main stream: w1/w2 transposes, usage, G1 -> G2 -> topk -> loss ----
    transpose_split<<<dim3(Id / 32, Hd / 32), dim3(32, 8)>>>(w1, Hd, Id, 3, 4, 0);
    transpose_split<<<dim3(Pd / 32, Id / 32), dim3(32, 8)>>>(w2, Id, Pd, 7, -1, 1);
    zero_usage_kernel<<<Pd / 256, 256>>>();

    gemm_mma<<<dim3(Id / 128, NTOK / 128), 256>>>(
        0x100u, 0x343u, 3, Hd, b1, nullptr, 0, Id, 1, 1);
    gemm_mma<<<dim3(Pd / 128, NTOK / 128), 256>>>(
        0x6u, 0x7u, 1, Id, b2, nullptr, 9, Pd, 0, 2);
    topk_kernel<<<NTOK, 256>>>(pool, temp, b2);
    const long long tsz = (long long)NTOK * Dd;
    loss_kernel<<<1, 512>>>(out + tsz, ((long long)out_size > tsz) ? 1 : 0);

    // ---- join: G4 needs ln + wm (side) and topk (main) ----
    cudaStreamWaitEvent(0, evJoin, 0);
    gemm_mma<<<dim3(Dd / 128, NTOK / 128), 256>>>(
        0xBAu, 0xCCu, 2, 2 * Dd, bm, out, 9, Dd, 0, 0);
}

// round 15
// speedup vs baseline: 1.0841x; 1.0004x over previous
#include <cuda_runtime.h>
#include <cuda_fp16.h>
#include <cstdint>
#include <cstddef>
#include <math.h>

#define NTOK 8192
#define Hd 2048
#define Id 1024
#define Pd 4096
#define Dd 1024

// ---------------- static device scratch (fp16 splits) ----------------
__device__ __half g_xa0[(size_t)NTOK * Hd];
__device__ __half g_xa1[(size_t)NTOK * Hd];
__device__ __half g_w1t0[(size_t)Id * Hd];
__device__ __half g_w1t1[(size_t)Id * Hd];
__device__ __half g_i0[(size_t)NTOK * Id];
__device__ __half g_w2t0[(size_t)Pd * Id];
__device__ float  g_w2tf[(size_t)Pd * Id];
__device__ __half g_wpt0[(size_t)Dd * Hd];
__device__ __half g_ca0[(size_t)NTOK * 2 * Dd];
__device__ __half g_ca1[(size_t)NTOK * 2 * Dd];
__device__ __half g_wmt0[(size_t)Dd * 2 * Dd];
__device__ __half g_lb[(size_t)NTOK * Pd];      // fp16 logits
__device__ float  g_inter[(size_t)NTOK * Id];
__device__ float  g_proj[(size_t)NTOK * Dd];
__device__ float  g_usage[Pd];

__device__ __forceinline__ __half* bufselw(int s) {
    switch (s) {
        case 0:  return g_xa0;  case 1:  return g_xa1;
        case 3:  return g_w1t0; case 4:  return g_w1t1;
        case 6:  return g_i0;   case 7:  return g_w2t0;
        case 8:  return g_wpt0;
        case 10: return g_ca0;  case 11: return g_ca1;
        default: return g_wmt0;
    }
}
__device__ __forceinline__ const __half* bufsel(int s) { return bufselw(s); }
__device__ __forceinline__ float* csel(int s, float* ext) {
    switch (s) {
        case 0: return g_inter;
        case 2: return g_proj;
        default: return ext;
    }
}

// ---------------- PTX helpers ----------------
__device__ __forceinline__ uint32_t smem_u32(const void* p) {
    uint32_t a;
    asm("{ .reg .u64 t; cvta.to.shared.u64 t, %1; cvt.u32.u64 %0, t; }" : "=r"(a) : "l"(p));
    return a;
}
#define CPA16(d, s) asm volatile("cp.async.cg.shared.global [%0], [%1], 16;" :: "r"(d), "l"(s) : "memory")
#define CPA_COMMIT() asm volatile("cp.async.commit_group;" ::: "memory")
#define CPA_WAIT2() asm volatile("cp.async.wait_group 2;" ::: "memory")
#define CPA_WAIT1() asm volatile("cp.async.wait_group 1;" ::: "memory")
#define CPA_WAIT0() asm volatile("cp.async.wait_group 0;" ::: "memory")

__device__ __forceinline__ void ldmx4(uint32_t* r, uint32_t addr) {
    asm volatile("ldmatrix.sync.aligned.m8n8.x4.shared.b16 {%0,%1,%2,%3}, [%4];"
                 : "=r"(r[0]), "=r"(r[1]), "=r"(r[2]), "=r"(r[3]) : "r"(addr));
}
__device__ __forceinline__ void mma16816(float* d, const uint32_t* a, const uint32_t* b) {
    asm volatile("mma.sync.aligned.m16n8k16.row.col.f32.f16.f16.f32 "
                 "{%0,%1,%2,%3}, {%4,%5,%6,%7}, {%8,%9}, {%0,%1,%2,%3};"
                 : "+f"(d[0]), "+f"(d[1]), "+f"(d[2]), "+f"(d[3])
                 : "r"(a[0]), "r"(a[1]), "r"(a[2]), "r"(a[3]), "r"(b[0]), "r"(b[1]));
}

// ---------------- HMMA GEMM: 128x128 tile, 4 warps (2x2), 64x64 per warp ----
// SMEM-read redundancy 32KB/chunk (was 48KB with 8 warps 2x4).
#define ST 3
#define STAGE_B 16384       // A 8KB + B 8KB

__device__ __forceinline__ uint32_t swzo(int row, int kcol) {
    return (uint32_t)(row * 64 + ((((kcol >> 3) ^ ((row >> 1) & 3)) << 4)) + ((kcol & 7) << 1));
}

__global__ void __launch_bounds__(128, 2)
gemm_mma(uint32_t aPack, uint32_t bPack, int npass, int K,
         const float* __restrict__ bias, float* Cext, int cselv, int ldc,
         int relu, int conv)   // conv: 0 none, 1 also fp16->g_i0, 2 fp16 ONLY ->g_lb
{
    __shared__ __align__(1024) char smem[ST * STAGE_B];
    const uint32_t sb = smem_u32(smem);
    const int tid = threadIdx.x, lane = tid & 31, wid = tid >> 5;
    const int wm = wid & 1, wn = wid >> 1;          // warp grid 2(M) x 2(N), 64x64 each
    const int bn = blockIdx.x, bm = blockIdx.y;
    float* C = csel(cselv, Cext);

    const int kcp = K >> 5;
    const int NCH = npass * kcp;

    float acc[4][8][4];
    #pragma unroll
    for (int i = 0; i < 4; i++)
        #pragma unroll
        for (int j = 0; j < 8; j++)
            #pragma unroll
            for (int q = 0; q < 4; q++) acc[i][j][q] = 0.0f;

    auto load_chunk = [&](int ch, int buf) {
        const int p = ch / kcp, kc = ch % kcp;
        const __half* A = bufsel((aPack >> (4 * p)) & 15) + (size_t)(bm * 128) * K + kc * 32;
        const __half* B = bufsel((bPack >> (4 * p)) & 15) + (size_t)(bn * 128) * K + kc * 32;
        const uint32_t ab = sb + buf * STAGE_B;
        const uint32_t bb = ab + 8192;
        #pragma unroll
        for (int i = 0; i < 4; i++) {
            const int g = tid + i * 128, r = g >> 2, c = g & 3;
            const uint32_t so = swzo(r, c * 8);
            CPA16(ab + so, A + (size_t)r * K + c * 8);
            CPA16(bb + so, B + (size_t)r * K + c * 8);
        }
        CPA_COMMIT();
    };

    load_chunk(0, 0);
    if (NCH > 1) load_chunk(1, 1);

    const int a_r = wm * 64 + (lane & 15);                      // + mt*16
    const int a_kc = (lane >> 4) * 8;                           // + ks*16
    const int b_r = wn * 64 + (lane & 7) + ((lane >> 4) << 3);  // + q*16
    const int b_kc = ((lane >> 3) & 1) * 8;                     // + ks*16

    for (int c = 0; c < NCH; c++) {
        if (c + 2 < NCH) { load_chunk(c + 2, (c + 2) % ST); CPA_WAIT2(); }
        else if (c + 1 < NCH) CPA_WAIT1();
        else CPA_WAIT0();
        __syncthreads();

        const uint32_t abase = sb + (c % ST) * STAGE_B;
        const uint32_t bbase = abase + 8192;
        #pragma unroll
        for (int ks = 0; ks < 2; ks++) {
            uint32_t af[4][4], bf[4][4];
            #pragma unroll
            for (int mt = 0; mt < 4; mt++)
                ldmx4(af[mt], abase + swzo(a_r + mt * 16, ks * 16 + a_kc));
            #pragma unroll
            for (int q = 0; q < 4; q++)
                ldmx4(bf[q], bbase + swzo(b_r + q * 16, ks * 16 + b_kc));
            #pragma unroll
            for (int mt = 0; mt < 4; mt++)
                #pragma unroll
                for (int nt = 0; nt < 8; nt++)
                    mma16816(acc[mt][nt], af[mt], &bf[nt >> 1][(nt & 1) * 2]);
        }
        __syncthreads();
    }

    #pragma unroll
    for (int mt = 0; mt < 4; mt++) {
        const int r0 = bm * 128 + wm * 64 + mt * 16 + (lane >> 2);
        #pragma unroll
        for (int nt = 0; nt < 8; nt++) {
            const int col = bn * 128 + wn * 64 + nt * 8 + (lane & 3) * 2;
            const float bb0 = bias[col], bb1 = bias[col + 1];
            float v0 = acc[mt][nt][0] + bb0, v1 = acc[mt][nt][1] + bb1;
            float v2 = acc[mt][nt][2] + bb0, v3 = acc[mt][nt][3] + bb1;
            if (relu) {
                v0 = fmaxf(v0, 0.f); v1 = fmaxf(v1, 0.f);
                v2 = fmaxf(v2, 0.f); v3 = fmaxf(v3, 0.f);
            }
            if (conv != 2) {
                *(float2*)(C + (size_t)r0 * ldc + col) = make_float2(v0, v1);
                *(float2*)(C + (size_t)(r0 + 8) * ldc + col) = make_float2(v2, v3);
            }
            if (conv) {
                __half* tb = (conv == 1) ? g_i0 : g_lb;
                *(__half2*)(tb + (size_t)r0 * ldc + col) =
                    __halves2half2(__float2half(v0), __float2half(v1));
                *(__half2*)(tb + (size_t)(r0 + 8) * ldc + col) =
                    __halves2half2(__float2half(v2), __float2half(v3));
            }
        }
    }
}

// ---------------- prep ----------------
__global__ void split_x2_kernel(const float* __restrict__ x) {
    size_t i = (size_t)blockIdx.x * blockDim.x + threadIdx.x;
    const size_t n = (size_t)NTOK * Hd;
    if (i >= n) return;
    float v = x[i];
    __half h0 = __float2half(v);
    g_xa0[i] = h0;
    g_xa1[i] = __float2half(v - __half2float(h0));
}

__global__ void transpose_split(const float* __restrict__ W, int R, int C,
                                int s0, int s1, int wf) {
    __half* T0 = bufselw(s0);
    __half* T1 = (s1 >= 0) ? bufselw(s1) : nullptr;
    float* TF = wf ? g_w2tf : nullptr;

    __shared__ float t[32][33];
    const int bx = blockIdx.x * 32, by = blockIdx.y * 32;
    const int tx = threadIdx.x, ty = threadIdx.y;
    #pragma unroll
    for (int i = 0; i < 4; i++)
        t[ty + i * 8][tx] = W[(size_t)(by + ty + i * 8) * C + bx + tx];
    __syncthreads();
    #pragma unroll
    for (int i = 0; i < 4; i++) {
        const int c = bx + ty + i * 8, r = by + tx;
        const float v = t[tx][ty + i * 8];
        const size_t o = (size_t)c * R + r;
        __half h0 = __float2half(v);
        T0[o] = h0;
        if (T1) T1[o] = __float2half(v - __half2float(h0));
        if (TF) TF[o] = v;
    }
}

// ---------------- reductions ----------------
template <int NT>
__device__ __forceinline__ float breduce(float v) {
    __shared__ float sh[NT];
    int tid = threadIdx.x;
    sh[tid] = v; __syncthreads();
    #pragma unroll
    for (int s = NT / 2; s > 0; s >>= 1) {
        if (tid < s) sh[tid] += sh[tid + s];
        __syncthreads();
    }
    float r = sh[0]; __syncthreads();
    return r;
}

__global__ void zero_usage_kernel() {
    int i = blockIdx.x * blockDim.x + threadIdx.x;
    if (i < Pd) g_usage[i] = 0.0f;
}

// ---------------- top-2: single-sweep (register-cached) + exact recompute ----
__global__ void __launch_bounds__(256)
topk_kernel(const float* __restrict__ pool, const float* __restrict__ temp_ptr,
            const float* __restrict__ b2)
{
    const int row = blockIdx.x, tid = threadIdx.x;
    const int wid = tid >> 5, lane = tid & 31;
    const __half* lrow = g_lb + (size_t)row * Pd;
    float t = temp_ptr[0];
    t = fminf(fmaxf(t, 0.1f), 5.0f);
    const float it = 1.0f / t;

    float cache[16];
    float v1 = -INFINITY, v2 = -INFINITY;
    #pragma unroll
    for (int itr = 0; itr < 8; itr++) {
        const int j = tid * 2 + itr * 512;
        __half2 p2 = *(const __half2*)(lrow + j);
        float va = fminf(fmaxf(__low2float(p2) * it, -10.0f), 10.0f);
        float vb = fminf(fmaxf(__high2float(p2) * it, -10.0f), 10.0f);
        cache[itr * 2] = va; cache[itr * 2 + 1] = vb;
        float hi = fmaxf(va, vb), lo = fminf(va, vb);
        if (hi > v1) { v2 = fmaxf(v1, lo); v1 = hi; }
        else v2 = fmaxf(v2, hi);
    }
    __shared__ float s1[256], s2[256];
    s1[tid] = v1; s2[tid] = v2; __syncthreads();
    for (int s = 128; s > 0; s >>= 1) {
        if (tid < s) {
            float a1 = s1[tid], a2 = s2[tid], b1v = s1[tid + s], b2v = s2[tid + s];
            s1[tid] = fmaxf(a1, b1v);
            s2[tid] = fmaxf(fminf(a1, b1v), fmaxf(a2, b2v));
        }
        __syncthreads();
    }
    const float thr = s2[0] - 0.02f * it;

    __shared__ int cands[64];
    __shared__ int ncand;
    if (tid == 0) ncand = 0;
    __syncthreads();
    #pragma unroll
    for (int itr = 0; itr < 8; itr++) {
        const int j = tid * 2 + itr * 512;
        if (cache[itr * 2] >= thr)     { int p = atomicAdd(&ncand, 1); if (p < 64) cands[p] = j; }
        if (cache[itr * 2 + 1] >= thr) { int p = atomicAdd(&ncand, 1); if (p < 64) cands[p] = j + 1; }
    }
    __syncthreads();
    const int nc = min(ncand, 64);

    __shared__ float exv[64];
    const float* irow = g_inter + (size_t)row * Id;
    for (int base = 0; base < nc; base += 8) {
        const int q = base + wid;
        if (q < nc) {
            const int j = cands[q];
            const float* wr = g_w2tf + (size_t)j * Id;
            float s = 0.0f;
            for (int k = lane; k < Id; k += 32) s += irow[k] * wr[k];
            #pragma unroll
            for (int o = 16; o > 0; o >>= 1) s += __shfl_down_sync(0xffffffffu, s, o);
            if (lane == 0) exv[q] = fminf(fmaxf((s + b2[j]) / t, -10.0f), 10.0f);
        }
    }
    __syncthreads();

    __shared__ float sw0, sw1;
    __shared__ int sj0, sj1;
    if (tid == 0) {
        float bv1 = -INFINITY, bv2 = -INFINITY;
        int bi1 = 0x7fffffff, bi2 = 0x7fffffff;
        for (int q = 0; q < nc; q++) {
            float v = exv[q]; int j = cands[q];
            if (v > bv1 || (v == bv1 && j < bi1)) {
                bv2 = bv1; bi2 = bi1; bv1 = v; bi1 = j;
            } else if (v > bv2 || (v == bv2 && j < bi2)) {
                bv2 = v; bi2 = j;
            }
        }
        float e = expf(bv2 - bv1), se = 1.0f + e;
        sw0 = 1.0f / se; sw1 = e / se; sj0 = bi1; sj1 = bi2;
        atomicAdd(&g_usage[bi1], sw0);
        atomicAdd(&g_usage[bi2], sw1);
    }
    __syncthreads();

    const float w0 = sw0, w1 = sw1;
    float4 a = ((const float4*)(pool + (size_t)sj0 * Dd))[tid];
    float4 b = ((const float4*)(pool + (size_t)sj1 * Dd))[tid];
    float ov[4] = { w0 * a.x + w1 * b.x, w0 * a.y + w1 * b.y,
                    w0 * a.z + w1 * b.z, w0 * a.w + w1 * b.w };
    const size_t off = (size_t)row * (2 * Dd) + Dd + tid * 4;
    #pragma unroll
    for (int q = 0; q < 4; q++) {
        __half h0 = __float2half(ov[q]);
        g_ca0[off + q] = h0;
        g_ca1[off + q] = __float2half(ov[q] - __half2float(h0));
    }
}

// ---------------- layernorm -> combined[:, 0:D] splits ----------------
__global__ void __launch_bounds__(256)
ln_kernel(const float* __restrict__ gamma, const float* __restrict__ beta)
{
    const int row = blockIdx.x, tid = threadIdx.x;
    float4 v = ((const float4*)(g_proj + (size_t)row * Dd))[tid];
    float s = v.x + v.y + v.z + v.w;
    s = breduce<256>(s);
    const float mean = s * (1.0f / Dd);
    float d0 = v.x - mean, d1 = v.y - mean, d2 = v.z - mean, d3 = v.w - mean;
    float q = d0 * d0 + d1 * d1 + d2 * d2 + d3 * d3;
    q = breduce<256>(q);
    const float rs = rsqrtf(q * (1.0f / Dd) + 1e-5f);
    float4 g = ((const float4*)gamma)[tid], b = ((const float4*)beta)[tid];
    float ov[4] = { d0 * rs * g.x + b.x, d1 * rs * g.y + b.y,
                    d2 * rs * g.z + b.z, d3 * rs * g.w + b.w };
    const size_t off = (size_t)row * (2 * Dd) + tid * 4;
    #pragma unroll
    for (int k = 0; k < 4; k++) {
        __half h0 = __float2half(ov[k]);
        g_ca0[off + k] = h0;
        g_ca1[off + k] = __float2half(ov[k] - __half2float(h0));
    }
}

// ---------------- diversity loss ----------------
__global__ void __launch_bounds__(512)
loss_kernel(float* __restrict__ out, int do_write)
{
    const int tid = threadIdx.x;
    float s = 0.0f;
    for (int j = tid; j < Pd; j += 512) s += g_usage[j];
    s = breduce<512>(s);
    const float denom = s + 1e-8f, uni = 1.0f / Pd;
    float q = 0.0f;
    for (int j = tid; j < Pd; j += 512) {
        float d = g_usage[j] / denom - uni;
        q += d * d;
    }
    q = breduce<512>(q);
    if (tid == 0 && do_write) out[0] = (q / Pd) * 0.01f;
}

// ---------------- launch (fork-join streams, graph-capturable) --------------
extern "C" void kernel_launch(void* const* d_in, const int* in_sizes, int n_in,
                              void* d_out, int out_size)
{
    const int o = (n_in >= 14) ? 1 : 0;
    const float* x     = (const float*)d_in[0];
    const float* pool  = (const float*)d_in[1];
    const float* w1    = (const float*)d_in[2 + o];
    const float* b1    = (const float*)d_in[3 + o];
    const float* w2    = (const float*)d_in[4 + o];
    const float* b2    = (const float*)d_in[5 + o];
    const float* temp  = (const float*)d_in[6 + o];
    const float* wp    = (const float*)d_in[7 + o];
    const float* bp    = (const float*)d_in[8 + o];
    const float* gamma = (const float*)d_in[9 + o];
    const float* beta  = (const float*)d_in[10 + o];
    const float* wm    = (const float*)d_in[11 + o];
    const float* bm    = (const float*)d_in[12 + o];
    float* out = (float*)d_out;

    static cudaStream_t sB = nullptr;
    static cudaEvent_t evFork = nullptr, evJoin = nullptr;
    if (!sB) {
        cudaStreamCreateWithFlags(&sB, cudaStreamNonBlocking);
        cudaEventCreateWithFlags(&evFork, cudaEventDisableTiming);
        cudaEventCreateWithFlags(&evJoin, cudaEventDisableTiming);
    }

    split_x2_kernel<<<((size_t)NTOK * Hd + 255) / 256, 256>>>(x);
    cudaEventRecord(evFork, 0);
    cudaStreamWaitEvent(sB, evFork, 0);

    // ---- side stream: wp transpose -> G3 -> ln -> wm transpose ----
    transpose_split<<<dim3(Dd / 32, Hd / 32), dim3(32, 8), 0, sB>>>(wp, Hd, Dd, 8, -1, 0);
    gemm_mma<<<dim3(Dd / 128, NTOK / 128), 128, 0, sB>>>(
        0x10u, 0x88u, 2, Hd, bp, nullptr, 2, Dd, 0, 0);
    ln_kernel<<<NTOK, 256, 0, sB>>>(gamma, beta);
    transpose_split<<<dim3(Dd / 32, (2 * Dd) / 32), dim3(32, 8), 0, sB>>>(wm, 2 * Dd, Dd, 12, -1, 0);
    cudaEventRecord(evJoin, sB);

    // ---- main stream: w1/w2 transposes, usage, G1 -> G2 -> topk -> loss ----
    transpose_split<<<dim3(Id / 32, Hd / 32), dim3(32, 8)>>>(w1, Hd, Id, 3, 4, 0);
    transpose_split<<<dim3(Pd / 32, Id / 32), dim3(32, 8)>>>(w2, Id, Pd, 7, -1, 1);
    zero_usage_kernel<<<Pd / 256, 256>>>();

    gemm_mma<<<dim3(Id / 128, NTOK / 128), 128>>>(
        0x100u, 0x343u, 3, Hd, b1, nullptr, 0, Id, 1, 1);
    gemm_mma<<<dim3(Pd / 128, NTOK / 128), 128>>>(
        0x6u, 0x7u, 1, Id, b2, nullptr, 9, Pd, 0, 2);
    topk_kernel<<<NTOK, 256>>>(pool, temp, b2);
    const long long tsz = (long long)NTOK * Dd;
    loss_kernel<<<1, 512>>>(out + tsz, ((long long)out_size > tsz) ? 1 : 0);

    // ---- join: G4 needs ln + wm (side) and topk (main) ----
    cudaStreamWaitEvent(0, evJoin, 0);
    gemm_mma<<<dim3(Dd / 128, NTOK / 128), 128>>>(
        0xBAu, 0xCCu, 2, 2 * Dd, bm, out, 9, Dd, 0, 0);
}

// round 16
// speedup vs baseline: 1.1703x; 1.0795x over previous
#include <cuda_runtime.h>
#include <cuda_fp16.h>
#include <cstdint>
#include <cstddef>
#include <math.h>

#define NTOK 8192
#define Hd 2048
#define Id 1024
#define Pd 4096
#define Dd 1024

// ---------------- static device scratch ----------------
__device__ __half g_xa0[(size_t)NTOK * Hd];
__device__ __half g_xa1[(size_t)NTOK * Hd];
__device__ __half g_w1t0[(size_t)Id * Hd];
__device__ __half g_w1t1[(size_t)Id * Hd];
__device__ __half g_i0[(size_t)NTOK * Id];
__device__ __half g_w2t0[(size_t)Pd * Id];
__device__ float  g_w2tf[(size_t)Pd * Id];
__device__ __half g_wpt0[(size_t)Dd * Hd];
__device__ __half g_ca0[(size_t)NTOK * Dd];          // ln output split hi
__device__ __half g_ca1[(size_t)NTOK * Dd];          // ln output split lo
__device__ __half g_wmt0[(size_t)Dd * 2 * Dd];       // wm^T [1024, 2048]
__device__ __half g_pp0[(size_t)Pd * Dd];            // pool split hi
__device__ __half g_pp1[(size_t)Pd * Dd];            // pool split lo
__device__ float  g_poolwm[(size_t)Pd * Dd];         // pool @ wm2  [4096,1024]
__device__ __half g_lb[(size_t)NTOK * Pd];           // fp16 logits
__device__ float  g_inter[(size_t)NTOK * Id];
__device__ float  g_proj[(size_t)NTOK * Dd];
__device__ float  g_usage[Pd];
__device__ float2 g_tw[NTOK];                        // (w0, w1)
__device__ int2   g_tj[NTOK];                        // (j0, j1)

__device__ __forceinline__ __half* bufselw(int s) {
    switch (s) {
        case 0:  return g_xa0;  case 1:  return g_xa1;
        case 2:  return g_pp0;  case 5:  return g_pp1;
        case 3:  return g_w1t0; case 4:  return g_w1t1;
        case 6:  return g_i0;   case 7:  return g_w2t0;
        case 8:  return g_wpt0;
        case 10: return g_ca0;  case 11: return g_ca1;
        default: return g_wmt0;
    }
}
__device__ __forceinline__ const __half* bufsel(int s) { return bufselw(s); }
__device__ __forceinline__ float* csel(int s, float* ext) {
    switch (s) {
        case 0: return g_inter;
        case 2: return g_proj;
        case 3: return g_poolwm;
        default: return ext;
    }
}

// ---------------- PTX helpers ----------------
__device__ __forceinline__ uint32_t smem_u32(const void* p) {
    uint32_t a;
    asm("{ .reg .u64 t; cvta.to.shared.u64 t, %1; cvt.u32.u64 %0, t; }" : "=r"(a) : "l"(p));
    return a;
}
#define CPA16(d, s) asm volatile("cp.async.cg.shared.global [%0], [%1], 16;" :: "r"(d), "l"(s) : "memory")
#define CPA_COMMIT() asm volatile("cp.async.commit_group;" ::: "memory")
#define CPA_WAIT2() asm volatile("cp.async.wait_group 2;" ::: "memory")
#define CPA_WAIT1() asm volatile("cp.async.wait_group 1;" ::: "memory")
#define CPA_WAIT0() asm volatile("cp.async.wait_group 0;" ::: "memory")

__device__ __forceinline__ void ldmx4(uint32_t* r, uint32_t addr) {
    asm volatile("ldmatrix.sync.aligned.m8n8.x4.shared.b16 {%0,%1,%2,%3}, [%4];"
                 : "=r"(r[0]), "=r"(r[1]), "=r"(r[2]), "=r"(r[3]) : "r"(addr));
}
__device__ __forceinline__ void mma16816(float* d, const uint32_t* a, const uint32_t* b) {
    asm volatile("mma.sync.aligned.m16n8k16.row.col.f32.f16.f16.f32 "
                 "{%0,%1,%2,%3}, {%4,%5,%6,%7}, {%8,%9}, {%0,%1,%2,%3};"
                 : "+f"(d[0]), "+f"(d[1]), "+f"(d[2]), "+f"(d[3])
                 : "r"(a[0]), "r"(a[1]), "r"(a[2]), "r"(a[3]), "r"(b[0]), "r"(b[1]));
}

// ---------------- HMMA GEMM (R11 proven loop; + lda/ldb/kOffB, gather epi) --
#define ST 3
#define STAGE_B 16384       // A 8KB + B 8KB

__device__ __forceinline__ uint32_t swzo(int row, int kcol) {
    return (uint32_t)(row * 64 + ((((kcol >> 3) ^ ((row >> 1) & 3)) << 4)) + ((kcol & 7) << 1));
}

// conv: 0 none, 1 also fp16->g_i0, 2 fp16 ONLY ->g_lb, 3 add pool-gather (G4)
__global__ void __launch_bounds__(256, 2)
gemm_mma(uint32_t aPack, uint32_t bPack, int npass, int K, int lda, int ldb, int kOffB,
         const float* __restrict__ bias, float* Cext, int cselv, int ldc,
         int relu, int conv)
{
    __shared__ __align__(1024) char smem[ST * STAGE_B];
    const uint32_t sb = smem_u32(smem);
    const int tid = threadIdx.x, lane = tid & 31, wid = tid >> 5;
    const int wm = wid & 1, wn = wid >> 1;
    const int bn = blockIdx.x, bm = blockIdx.y;
    float* C = csel(cselv, Cext);

    const int kcp = K >> 5;
    const int NCH = npass * kcp;

    float acc[4][4][4];
    #pragma unroll
    for (int i = 0; i < 4; i++)
        #pragma unroll
        for (int j = 0; j < 4; j++)
            #pragma unroll
            for (int q = 0; q < 4; q++) acc[i][j][q] = 0.0f;

    auto load_chunk = [&](int ch, int buf) {
        const int p = ch / kcp, kc = ch % kcp;
        const __half* A = bufsel((aPack >> (4 * p)) & 15) + (size_t)(bm * 128) * lda + kc * 32;
        const __half* B = bufsel((bPack >> (4 * p)) & 15) + (size_t)(bn * 128) * ldb + kOffB + kc * 32;
        const uint32_t ab = sb + buf * STAGE_B;
        const uint32_t bb = ab + 8192;
        #pragma unroll
        for (int i = 0; i < 2; i++) {
            const int g = tid + i * 256, r = g >> 2, c = g & 3;
            const uint32_t so = swzo(r, c * 8);
            CPA16(ab + so, A + (size_t)r * lda + c * 8);
            CPA16(bb + so, B + (size_t)r * ldb + c * 8);
        }
        CPA_COMMIT();
    };

    load_chunk(0, 0);
    if (NCH > 1) load_chunk(1, 1);

    const int a_r = wm * 64 + (lane & 15);
    const int a_kc = (lane >> 4) * 8;
    const int b_r = wn * 32 + (lane & 7) + ((lane >> 4) << 3);
    const int b_kc = ((lane >> 3) & 1) * 8;

    for (int c = 0; c < NCH; c++) {
        if (c + 2 < NCH) { load_chunk(c + 2, (c + 2) % ST); CPA_WAIT2(); }
        else if (c + 1 < NCH) CPA_WAIT1();
        else CPA_WAIT0();
        __syncthreads();

        const uint32_t abase = sb + (c % ST) * STAGE_B;
        const uint32_t bbase = abase + 8192;
        #pragma unroll
        for (int ks = 0; ks < 2; ks++) {
            uint32_t af[4][4], bf[2][4];
            #pragma unroll
            for (int mt = 0; mt < 4; mt++)
                ldmx4(af[mt], abase + swzo(a_r + mt * 16, ks * 16 + a_kc));
            #pragma unroll
            for (int q = 0; q < 2; q++)
                ldmx4(bf[q], bbase + swzo(b_r + q * 16, ks * 16 + b_kc));
            #pragma unroll
            for (int mt = 0; mt < 4; mt++)
                #pragma unroll
                for (int nt = 0; nt < 4; nt++)
                    mma16816(acc[mt][nt], af[mt], &bf[nt >> 1][(nt & 1) * 2]);
        }
        __syncthreads();
    }

    #pragma unroll
    for (int mt = 0; mt < 4; mt++) {
        const int r0 = bm * 128 + wm * 64 + mt * 16 + (lane >> 2);
        // pool-gather weights for conv==3 (rows r0 and r0+8)
        float gw0 = 0.f, gw1 = 0.f, hw0 = 0.f, hw1 = 0.f;
        const float *pwA0 = nullptr, *pwA1 = nullptr, *pwB0 = nullptr, *pwB1 = nullptr;
        if (conv == 3) {
            float2 twa = g_tw[r0];     int2 tja = g_tj[r0];
            float2 twb = g_tw[r0 + 8]; int2 tjb = g_tj[r0 + 8];
            gw0 = twa.x; gw1 = twa.y; hw0 = twb.x; hw1 = twb.y;
            pwA0 = g_poolwm + (size_t)tja.x * Dd;
            pwA1 = g_poolwm + (size_t)tja.y * Dd;
            pwB0 = g_poolwm + (size_t)tjb.x * Dd;
            pwB1 = g_poolwm + (size_t)tjb.y * Dd;
        }
        #pragma unroll
        for (int nt = 0; nt < 4; nt++) {
            const int col = bn * 128 + wn * 32 + nt * 8 + (lane & 3) * 2;
            const float bb0 = bias ? bias[col] : 0.f;
            const float bb1 = bias ? bias[col + 1] : 0.f;
            float v0 = acc[mt][nt][0] + bb0, v1 = acc[mt][nt][1] + bb1;
            float v2 = acc[mt][nt][2] + bb0, v3 = acc[mt][nt][3] + bb1;
            if (relu) {
                v0 = fmaxf(v0, 0.f); v1 = fmaxf(v1, 0.f);
                v2 = fmaxf(v2, 0.f); v3 = fmaxf(v3, 0.f);
            }
            if (conv == 3) {
                v0 += gw0 * pwA0[col] + gw1 * pwA1[col];
                v1 += gw0 * pwA0[col + 1] + gw1 * pwA1[col + 1];
                v2 += hw0 * pwB0[col] + hw1 * pwB1[col];
                v3 += hw0 * pwB0[col + 1] + hw1 * pwB1[col + 1];
            }
            if (conv != 2) {
                *(float2*)(C + (size_t)r0 * ldc + col) = make_float2(v0, v1);
                *(float2*)(C + (size_t)(r0 + 8) * ldc + col) = make_float2(v2, v3);
            }
            if (conv == 1 || conv == 2) {
                __half* tb = (conv == 1) ? g_i0 : g_lb;
                *(__half2*)(tb + (size_t)r0 * ldc + col) =
                    __halves2half2(__float2half(v0), __float2half(v1));
                *(__half2*)(tb + (size_t)(r0 + 8) * ldc + col) =
                    __halves2half2(__float2half(v2), __float2half(v3));
            }
        }
    }
}

// ---------------- prep ----------------
__global__ void split_x2_kernel(const float* __restrict__ x) {
    size_t i = (size_t)blockIdx.x * blockDim.x + threadIdx.x;
    const size_t n = (size_t)NTOK * Hd;
    if (i >= n) return;
    float v = x[i];
    __half h0 = __float2half(v);
    g_xa0[i] = h0;
    g_xa1[i] = __float2half(v - __half2float(h0));
}

__global__ void split_pool_kernel(const float* __restrict__ pool) {
    size_t i = (size_t)blockIdx.x * blockDim.x + threadIdx.x;
    const size_t n = (size_t)Pd * Dd;
    if (i >= n) return;
    float v = pool[i];
    __half h0 = __float2half(v);
    g_pp0[i] = h0;
    g_pp1[i] = __float2half(v - __half2float(h0));
}

__global__ void transpose_split(const float* __restrict__ W, int R, int C,
                                int s0, int s1, int wf) {
    __half* T0 = bufselw(s0);
    __half* T1 = (s1 >= 0) ? bufselw(s1) : nullptr;
    float* TF = wf ? g_w2tf : nullptr;

    __shared__ float t[32][33];
    const int bx = blockIdx.x * 32, by = blockIdx.y * 32;
    const int tx = threadIdx.x, ty = threadIdx.y;
    #pragma unroll
    for (int i = 0; i < 4; i++)
        t[ty + i * 8][tx] = W[(size_t)(by + ty + i * 8) * C + bx + tx];
    __syncthreads();
    #pragma unroll
    for (int i = 0; i < 4; i++) {
        const int c = bx + ty + i * 8, r = by + tx;
        const float v = t[tx][ty + i * 8];
        const size_t o = (size_t)c * R + r;
        __half h0 = __float2half(v);
        T0[o] = h0;
        if (T1) T1[o] = __float2half(v - __half2float(h0));
        if (TF) TF[o] = v;
    }
}

// ---------------- reductions ----------------
template <int NT>
__device__ __forceinline__ float breduce(float v) {
    __shared__ float sh[NT];
    int tid = threadIdx.x;
    sh[tid] = v; __syncthreads();
    #pragma unroll
    for (int s = NT / 2; s > 0; s >>= 1) {
        if (tid < s) sh[tid] += sh[tid + s];
        __syncthreads();
    }
    float r = sh[0]; __syncthreads();
    return r;
}

__global__ void zero_usage_kernel() {
    int i = blockIdx.x * blockDim.x + threadIdx.x;
    if (i < Pd) g_usage[i] = 0.0f;
}

// ---------------- top-2: single-sweep + exact recompute; emits (j,w) --------
__global__ void __launch_bounds__(256)
topk_kernel(const float* __restrict__ temp_ptr, const float* __restrict__ b2)
{
    const int row = blockIdx.x, tid = threadIdx.x;
    const int wid = tid >> 5, lane = tid & 31;
    const __half* lrow = g_lb + (size_t)row * Pd;
    float t = temp_ptr[0];
    t = fminf(fmaxf(t, 0.1f), 5.0f);
    const float it = 1.0f / t;

    float cache[16];
    float v1 = -INFINITY, v2 = -INFINITY;
    #pragma unroll
    for (int itr = 0; itr < 8; itr++) {
        const int j = tid * 2 + itr * 512;
        __half2 p2 = *(const __half2*)(lrow + j);
        float va = fminf(fmaxf(__low2float(p2) * it, -10.0f), 10.0f);
        float vb = fminf(fmaxf(__high2float(p2) * it, -10.0f), 10.0f);
        cache[itr * 2] = va; cache[itr * 2 + 1] = vb;
        float hi = fmaxf(va, vb), lo = fminf(va, vb);
        if (hi > v1) { v2 = fmaxf(v1, lo); v1 = hi; }
        else v2 = fmaxf(v2, hi);
    }
    __shared__ float s1[256], s2[256];
    s1[tid] = v1; s2[tid] = v2; __syncthreads();
    for (int s = 128; s > 0; s >>= 1) {
        if (tid < s) {
            float a1 = s1[tid], a2 = s2[tid], b1v = s1[tid + s], b2v = s2[tid + s];
            s1[tid] = fmaxf(a1, b1v);
            s2[tid] = fmaxf(fminf(a1, b1v), fmaxf(a2, b2v));
        }
        __syncthreads();
    }
    const float thr = s2[0] - 0.02f * it;

    __shared__ int cands[64];
    __shared__ int ncand;
    if (tid == 0) ncand = 0;
    __syncthreads();
    #pragma unroll
    for (int itr = 0; itr < 8; itr++) {
        const int j = tid * 2 + itr * 512;
        if (cache[itr * 2] >= thr)     { int p = atomicAdd(&ncand, 1); if (p < 64) cands[p] = j; }
        if (cache[itr * 2 + 1] >= thr) { int p = atomicAdd(&ncand, 1); if (p < 64) cands[p] = j + 1; }
    }
    __syncthreads();
    const int nc = min(ncand, 64);

    __shared__ float exv[64];
    const float* irow = g_inter + (size_t)row * Id;
    for (int base = 0; base < nc; base += 8) {
        const int q = base + wid;
        if (q < nc) {
            const int j = cands[q];
            const float* wr = g_w2tf + (size_t)j * Id;
            float s = 0.0f;
            for (int k = lane; k < Id; k += 32) s += irow[k] * wr[k];
            #pragma unroll
            for (int o = 16; o > 0; o >>= 1) s += __shfl_down_sync(0xffffffffu, s, o);
            if (lane == 0) exv[q] = fminf(fmaxf((s + b2[j]) / t, -10.0f), 10.0f);
        }
    }
    __syncthreads();

    if (tid == 0) {
        float bv1 = -INFINITY, bv2 = -INFINITY;
        int bi1 = 0x7fffffff, bi2 = 0x7fffffff;
        for (int q = 0; q < nc; q++) {
            float v = exv[q]; int j = cands[q];
            if (v > bv1 || (v == bv1 && j < bi1)) {
                bv2 = bv1; bi2 = bi1; bv1 = v; bi1 = j;
            } else if (v > bv2 || (v == bv2 && j < bi2)) {
                bv2 = v; bi2 = j;
            }
        }
        float e = expf(bv2 - bv1), se = 1.0f + e;
        float w0 = 1.0f / se, w1 = e / se;
        g_tw[row] = make_float2(w0, w1);
        g_tj[row] = make_int2(bi1, bi2);
        atomicAdd(&g_usage[bi1], w0);
        atomicAdd(&g_usage[bi2], w1);
    }
}

// ---------------- layernorm -> ca0/ca1 [NTOK, Dd] ----------------
__global__ void __launch_bounds__(256)
ln_kernel(const float* __restrict__ gamma, const float* __restrict__ beta)
{
    const int row = blockIdx.x, tid = threadIdx.x;
    float4 v = ((const float4*)(g_proj + (size_t)row * Dd))[tid];
    float s = v.x + v.y + v.z + v.w;
    s = breduce<256>(s);
    const float mean = s * (1.0f / Dd);
    float d0 = v.x - mean, d1 = v.y - mean, d2 = v.z - mean, d3 = v.w - mean;
    float q = d0 * d0 + d1 * d1 + d2 * d2 + d3 * d3;
    q = breduce<256>(q);
    const float rs = rsqrtf(q * (1.0f / Dd) + 1e-5f);
    float4 g = ((const float4*)gamma)[tid], b = ((const float4*)beta)[tid];
    float ov[4] = { d0 * rs * g.x + b.x, d1 * rs * g.y + b.y,
                    d2 * rs * g.z + b.z, d3 * rs * g.w + b.w };
    const size_t off = (size_t)row * Dd + tid * 4;
    #pragma unroll
    for (int k = 0; k < 4; k++) {
        __half h0 = __float2half(ov[k]);
        g_ca0[off + k] = h0;
        g_ca1[off + k] = __float2half(ov[k] - __half2float(h0));
    }
}

// ---------------- diversity loss ----------------
__global__ void __launch_bounds__(512)
loss_kernel(float* __restrict__ out, int do_write)
{
    const int tid = threadIdx.x;
    float s = 0.0f;
    for (int j = tid; j < Pd; j += 512) s += g_usage[j];
    s = breduce<512>(s);
    const float denom = s + 1e-8f, uni = 1.0f / Pd;
    float q = 0.0f;
    for (int j = tid; j < Pd; j += 512) {
        float d = g_usage[j] / denom - uni;
        q += d * d;
    }
    q = breduce<512>(q);
    if (tid == 0 && do_write) out[0] = (q / Pd) * 0.01f;
}

// ---------------- launch (fork-join streams, graph-capturable) --------------
extern "C" void kernel_launch(void* const* d_in, const int* in_sizes, int n_in,
                              void* d_out, int out_size)
{
    const int o = (n_in >= 14) ? 1 : 0;
    const float* x     = (const float*)d_in[0];
    const float* pool  = (const float*)d_in[1];
    const float* w1    = (const float*)d_in[2 + o];
    const float* b1    = (const float*)d_in[3 + o];
    const float* w2    = (const float*)d_in[4 + o];
    const float* b2    = (const float*)d_in[5 + o];
    const float* temp  = (const float*)d_in[6 + o];
    const float* wp    = (const float*)d_in[7 + o];
    const float* bp    = (const float*)d_in[8 + o];
    const float* gamma = (const float*)d_in[9 + o];
    const float* beta  = (const float*)d_in[10 + o];
    const float* wm    = (const float*)d_in[11 + o];
    const float* bm    = (const float*)d_in[12 + o];
    float* out = (float*)d_out;

    static cudaStream_t sB = nullptr;
    static cudaEvent_t evFork = nullptr, evJoin = nullptr;
    if (!sB) {
        cudaStreamCreateWithFlags(&sB, cudaStreamNonBlocking);
        cudaEventCreateWithFlags(&evFork, cudaEventDisableTiming);
        cudaEventCreateWithFlags(&evJoin, cudaEventDisableTiming);
    }

    split_x2_kernel<<<((size_t)NTOK * Hd + 255) / 256, 256>>>(x);
    cudaEventRecord(evFork, 0);
    cudaStreamWaitEvent(sB, evFork, 0);

    // ---- side stream: wp_t -> G3 -> ln -> wm_t -> pool split -> poolwm ----
    transpose_split<<<dim3(Dd / 32, Hd / 32), dim3(32, 8), 0, sB>>>(wp, Hd, Dd, 8, -1, 0);
    gemm_mma<<<dim3(Dd / 128, NTOK / 128), 256, 0, sB>>>(
        0x10u, 0x88u, 2, Hd, Hd, Hd, 0, bp, nullptr, 2, Dd, 0, 0);
    ln_kernel<<<NTOK, 256, 0, sB>>>(gamma, beta);
    transpose_split<<<dim3(Dd / 32, (2 * Dd) / 32), dim3(32, 8), 0, sB>>>(wm, 2 * Dd, Dd, 12, -1, 0);
    split_pool_kernel<<<((size_t)Pd * Dd + 255) / 256, 256, 0, sB>>>(pool);
    // poolwm = pool @ wm2^T-half: A=pp0/pp1 (lda=Dd), B=wmt0 rows, kOffB=Dd (ldb=2Dd)
    gemm_mma<<<dim3(Dd / 128, Pd / 128), 256, 0, sB>>>(
        0x52u, 0xCCu, 2, Dd, Dd, 2 * Dd, Dd, nullptr, nullptr, 3, Dd, 0, 0);
    cudaEventRecord(evJoin, sB);

    // ---- main stream: w1/w2 transposes, usage, G1 -> G2 -> topk -> loss ----
    transpose_split<<<dim3(Id / 32, Hd / 32), dim3(32, 8)>>>(w1, Hd, Id, 3, 4, 0);
    transpose_split<<<dim3(Pd / 32, Id / 32), dim3(32, 8)>>>(w2, Id, Pd, 7, -1, 1);
    zero_usage_kernel<<<Pd / 256, 256>>>();

    gemm_mma<<<dim3(Id / 128, NTOK / 128), 256>>>(
        0x100u, 0x343u, 3, Hd, Hd, Hd, 0, b1, nullptr, 0, Id, 1, 1);
    gemm_mma<<<dim3(Pd / 128, NTOK / 128), 256>>>(
        0x6u, 0x7u, 1, Id, Id, Id, 0, b2, nullptr, 9, Pd, 0, 2);
    topk_kernel<<<NTOK, 256>>>(temp, b2);
    const long long tsz = (long long)NTOK * Dd;
    loss_kernel<<<1, 512>>>(out + tsz, ((long long)out_size > tsz) ? 1 : 0);

    // ---- join: G4' = ln_proj @ wm1 + bm + pool-gather (epilogue) ----
    cudaStreamWaitEvent(0, evJoin, 0);
    gemm_mma<<<dim3(Dd / 128, NTOK / 128), 256>>>(
        0xBAu, 0xCCu, 2, Dd, Dd, 2 * Dd, 0, bm, out, 9, Dd, 0, 3);
}

// round 17
// speedup vs baseline: 1.2950x; 1.1065x over previous
#include <cuda_runtime.h>
#include <cuda_fp16.h>
#include <cstdint>
#include <cstddef>
#include <math.h>

#define NTOK 8192
#define Hd 2048
#define Id 1024
#define Pd 4096
#define Dd 1024

// ---------------- static device scratch ----------------
__device__ __half g_xa0[(size_t)NTOK * Hd];
__device__ __half g_xa1[(size_t)NTOK * Hd];
__device__ __half g_w1t0[(size_t)Id * Hd];
__device__ __half g_w1t1[(size_t)Id * Hd];
__device__ __half g_i0[(size_t)NTOK * Id];
__device__ __half g_w2t0[(size_t)Pd * Id];
__device__ float  g_w2tf[(size_t)Pd * Id];
__device__ __half g_wpt0[(size_t)Dd * Hd];
__device__ __half g_ca0[(size_t)NTOK * Dd];          // ln output split hi
__device__ __half g_ca1[(size_t)NTOK * Dd];          // ln output split lo
__device__ __half g_wmt0[(size_t)Dd * 2 * Dd];       // wm^T [1024, 2048]
__device__ __half g_pp0[(size_t)Pd * Dd];            // pool split hi
__device__ __half g_pp1[(size_t)Pd * Dd];            // pool split lo
__device__ float  g_poolwm[(size_t)Pd * Dd];         // pool @ wm2  [4096,1024]
__device__ __half g_lb[(size_t)NTOK * Pd];           // fp16 logits
__device__ float  g_inter[(size_t)NTOK * Id];
__device__ float  g_proj[(size_t)NTOK * Dd];
__device__ float  g_usage[Pd];
__device__ float2 g_tw[NTOK];
__device__ int2   g_tj[NTOK];

__device__ __forceinline__ __half* bufselw(int s) {
    switch (s) {
        case 0:  return g_xa0;  case 1:  return g_xa1;
        case 2:  return g_pp0;  case 5:  return g_pp1;
        case 3:  return g_w1t0; case 4:  return g_w1t1;
        case 6:  return g_i0;   case 7:  return g_w2t0;
        case 8:  return g_wpt0;
        case 10: return g_ca0;  case 11: return g_ca1;
        default: return g_wmt0;
    }
}
__device__ __forceinline__ const __half* bufsel(int s) { return bufselw(s); }
__device__ __forceinline__ float* csel(int s, float* ext) {
    switch (s) {
        case 0: return g_inter;
        case 2: return g_proj;
        case 3: return g_poolwm;
        default: return ext;
    }
}

// ---------------- PTX helpers ----------------
__device__ __forceinline__ uint32_t smem_u32(const void* p) {
    uint32_t a;
    asm("{ .reg .u64 t; cvta.to.shared.u64 t, %1; cvt.u32.u64 %0, t; }" : "=r"(a) : "l"(p));
    return a;
}
#define CPA16(d, s) asm volatile("cp.async.cg.shared.global [%0], [%1], 16;" :: "r"(d), "l"(s) : "memory")
#define CPA_COMMIT() asm volatile("cp.async.commit_group;" ::: "memory")
#define CPA_WAIT2() asm volatile("cp.async.wait_group 2;" ::: "memory")
#define CPA_WAIT1() asm volatile("cp.async.wait_group 1;" ::: "memory")
#define CPA_WAIT0() asm volatile("cp.async.wait_group 0;" ::: "memory")

__device__ __forceinline__ void ldmx4(uint32_t* r, uint32_t addr) {
    asm volatile("ldmatrix.sync.aligned.m8n8.x4.shared.b16 {%0,%1,%2,%3}, [%4];"
                 : "=r"(r[0]), "=r"(r[1]), "=r"(r[2]), "=r"(r[3]) : "r"(addr));
}
__device__ __forceinline__ void mma16816(float* d, const uint32_t* a, const uint32_t* b) {
    asm volatile("mma.sync.aligned.m16n8k16.row.col.f32.f16.f16.f32 "
                 "{%0,%1,%2,%3}, {%4,%5,%6,%7}, {%8,%9}, {%0,%1,%2,%3};"
                 : "+f"(d[0]), "+f"(d[1]), "+f"(d[2]), "+f"(d[3])
                 : "r"(a[0]), "r"(a[1]), "r"(a[2]), "r"(a[3]), "r"(b[0]), "r"(b[1]));
}

// ---------------- HMMA GEMM (R11 loop; lda/ldb/kOffB, gather epilogue) ------
#define ST 3
#define STAGE_B 16384

__device__ __forceinline__ uint32_t swzo(int row, int kcol) {
    return (uint32_t)(row * 64 + ((((kcol >> 3) ^ ((row >> 1) & 3)) << 4)) + ((kcol & 7) << 1));
}

// conv: 0 none, 1 also fp16->g_i0, 2 fp16 ONLY ->g_lb, 3 add pool-gather (G4)
__global__ void __launch_bounds__(256, 2)
gemm_mma(uint32_t aPack, uint32_t bPack, int npass, int K, int lda, int ldb, int kOffB,
         const float* __restrict__ bias, float* Cext, int cselv, int ldc,
         int relu, int conv)
{
    __shared__ __align__(1024) char smem[ST * STAGE_B];
    const uint32_t sb = smem_u32(smem);
    const int tid = threadIdx.x, lane = tid & 31, wid = tid >> 5;
    const int wm = wid & 1, wn = wid >> 1;
    const int bn = blockIdx.x, bm = blockIdx.y;
    float* C = csel(cselv, Cext);

    const int kcp = K >> 5;
    const int NCH = npass * kcp;

    float acc[4][4][4];
    #pragma unroll
    for (int i = 0; i < 4; i++)
        #pragma unroll
        for (int j = 0; j < 4; j++)
            #pragma unroll
            for (int q = 0; q < 4; q++) acc[i][j][q] = 0.0f;

    auto load_chunk = [&](int ch, int buf) {
        const int p = ch / kcp, kc = ch % kcp;
        const __half* A = bufsel((aPack >> (4 * p)) & 15) + (size_t)(bm * 128) * lda + kc * 32;
        const __half* B = bufsel((bPack >> (4 * p)) & 15) + (size_t)(bn * 128) * ldb + kOffB + kc * 32;
        const uint32_t ab = sb + buf * STAGE_B;
        const uint32_t bb = ab + 8192;
        #pragma unroll
        for (int i = 0; i < 2; i++) {
            const int g = tid + i * 256, r = g >> 2, c = g & 3;
            const uint32_t so = swzo(r, c * 8);
            CPA16(ab + so, A + (size_t)r * lda + c * 8);
            CPA16(bb + so, B + (size_t)r * ldb + c * 8);
        }
        CPA_COMMIT();
    };

    load_chunk(0, 0);
    if (NCH > 1) load_chunk(1, 1);

    const int a_r = wm * 64 + (lane & 15);
    const int a_kc = (lane >> 4) * 8;
    const int b_r = wn * 32 + (lane & 7) + ((lane >> 4) << 3);
    const int b_kc = ((lane >> 3) & 1) * 8;

    for (int c = 0; c < NCH; c++) {
        if (c + 2 < NCH) { load_chunk(c + 2, (c + 2) % ST); CPA_WAIT2(); }
        else if (c + 1 < NCH) CPA_WAIT1();
        else CPA_WAIT0();
        __syncthreads();

        const uint32_t abase = sb + (c % ST) * STAGE_B;
        const uint32_t bbase = abase + 8192;
        #pragma unroll
        for (int ks = 0; ks < 2; ks++) {
            uint32_t af[4][4], bf[2][4];
            #pragma unroll
            for (int mt = 0; mt < 4; mt++)
                ldmx4(af[mt], abase + swzo(a_r + mt * 16, ks * 16 + a_kc));
            #pragma unroll
            for (int q = 0; q < 2; q++)
                ldmx4(bf[q], bbase + swzo(b_r + q * 16, ks * 16 + b_kc));
            #pragma unroll
            for (int mt = 0; mt < 4; mt++)
                #pragma unroll
                for (int nt = 0; nt < 4; nt++)
                    mma16816(acc[mt][nt], af[mt], &bf[nt >> 1][(nt & 1) * 2]);
        }
        __syncthreads();
    }

    #pragma unroll
    for (int mt = 0; mt < 4; mt++) {
        const int r0 = bm * 128 + wm * 64 + mt * 16 + (lane >> 2);
        float gw0 = 0.f, gw1 = 0.f, hw0 = 0.f, hw1 = 0.f;
        const float *pwA0 = nullptr, *pwA1 = nullptr, *pwB0 = nullptr, *pwB1 = nullptr;
        if (conv == 3) {
            float2 twa = g_tw[r0];     int2 tja = g_tj[r0];
            float2 twb = g_tw[r0 + 8]; int2 tjb = g_tj[r0 + 8];
            gw0 = twa.x; gw1 = twa.y; hw0 = twb.x; hw1 = twb.y;
            pwA0 = g_poolwm + (size_t)tja.x * Dd;
            pwA1 = g_poolwm + (size_t)tja.y * Dd;
            pwB0 = g_poolwm + (size_t)tjb.x * Dd;
            pwB1 = g_poolwm + (size_t)tjb.y * Dd;
        }
        #pragma unroll
        for (int nt = 0; nt < 4; nt++) {
            const int col = bn * 128 + wn * 32 + nt * 8 + (lane & 3) * 2;
            const float bb0 = bias ? bias[col] : 0.f;
            const float bb1 = bias ? bias[col + 1] : 0.f;
            float v0 = acc[mt][nt][0] + bb0, v1 = acc[mt][nt][1] + bb1;
            float v2 = acc[mt][nt][2] + bb0, v3 = acc[mt][nt][3] + bb1;
            if (relu) {
                v0 = fmaxf(v0, 0.f); v1 = fmaxf(v1, 0.f);
                v2 = fmaxf(v2, 0.f); v3 = fmaxf(v3, 0.f);
            }
            if (conv == 3) {
                v0 += gw0 * pwA0[col] + gw1 * pwA1[col];
                v1 += gw0 * pwA0[col + 1] + gw1 * pwA1[col + 1];
                v2 += hw0 * pwB0[col] + hw1 * pwB1[col];
                v3 += hw0 * pwB0[col + 1] + hw1 * pwB1[col + 1];
            }
            if (conv != 2) {
                *(float2*)(C + (size_t)r0 * ldc + col) = make_float2(v0, v1);
                *(float2*)(C + (size_t)(r0 + 8) * ldc + col) = make_float2(v2, v3);
            }
            if (conv == 1 || conv == 2) {
                __half* tb = (conv == 1) ? g_i0 : g_lb;
                *(__half2*)(tb + (size_t)r0 * ldc + col) =
                    __halves2half2(__float2half(v0), __float2half(v1));
                *(__half2*)(tb + (size_t)(r0 + 8) * ldc + col) =
                    __halves2half2(__float2half(v2), __float2half(v3));
            }
        }
    }
}

// ---------------- prep ----------------
__global__ void split_x2_kernel(const float* __restrict__ x) {
    size_t i = (size_t)blockIdx.x * blockDim.x + threadIdx.x;
    const size_t n = (size_t)NTOK * Hd;
    if (i >= n) return;
    float v = x[i];
    __half h0 = __float2half(v);
    g_xa0[i] = h0;
    g_xa1[i] = __float2half(v - __half2float(h0));
}

__global__ void split_pool_kernel(const float* __restrict__ pool) {
    size_t i = (size_t)blockIdx.x * blockDim.x + threadIdx.x;
    const size_t n = (size_t)Pd * Dd;
    if (i >= n) return;
    float v = pool[i];
    __half h0 = __float2half(v);
    g_pp0[i] = h0;
    g_pp1[i] = __float2half(v - __half2float(h0));
}

__global__ void transpose_split(const float* __restrict__ W, int R, int C,
                                int s0, int s1, int wf) {
    __half* T0 = bufselw(s0);
    __half* T1 = (s1 >= 0) ? bufselw(s1) : nullptr;
    float* TF = wf ? g_w2tf : nullptr;

    __shared__ float t[32][33];
    const int bx = blockIdx.x * 32, by = blockIdx.y * 32;
    const int tx = threadIdx.x, ty = threadIdx.y;
    #pragma unroll
    for (int i = 0; i < 4; i++)
        t[ty + i * 8][tx] = W[(size_t)(by + ty + i * 8) * C + bx + tx];
    __syncthreads();
    #pragma unroll
    for (int i = 0; i < 4; i++) {
        const int c = bx + ty + i * 8, r = by + tx;
        const float v = t[tx][ty + i * 8];
        const size_t o = (size_t)c * R + r;
        __half h0 = __float2half(v);
        T0[o] = h0;
        if (T1) T1[o] = __float2half(v - __half2float(h0));
        if (TF) TF[o] = v;
    }
}

// ---------------- reductions ----------------
template <int NT>
__device__ __forceinline__ float breduce(float v) {
    __shared__ float sh[NT];
    int tid = threadIdx.x;
    sh[tid] = v; __syncthreads();
    #pragma unroll
    for (int s = NT / 2; s > 0; s >>= 1) {
        if (tid < s) sh[tid] += sh[tid + s];
        __syncthreads();
    }
    float r = sh[0]; __syncthreads();
    return r;
}

__global__ void zero_usage_kernel() {
    int i = blockIdx.x * blockDim.x + threadIdx.x;
    if (i < Pd) g_usage[i] = 0.0f;
}

// ---------------- top-2: single-sweep + exact recompute; emits (j,w) --------
__global__ void __launch_bounds__(256)
topk_kernel(const float* __restrict__ temp_ptr, const float* __restrict__ b2)
{
    const int row = blockIdx.x, tid = threadIdx.x;
    const int wid = tid >> 5, lane = tid & 31;
    const __half* lrow = g_lb + (size_t)row * Pd;
    float t = temp_ptr[0];
    t = fminf(fmaxf(t, 0.1f), 5.0f);
    const float it = 1.0f / t;

    float cache[16];
    float v1 = -INFINITY, v2 = -INFINITY;
    #pragma unroll
    for (int itr = 0; itr < 8; itr++) {
        const int j = tid * 2 + itr * 512;
        __half2 p2 = *(const __half2*)(lrow + j);
        float va = fminf(fmaxf(__low2float(p2) * it, -10.0f), 10.0f);
        float vb = fminf(fmaxf(__high2float(p2) * it, -10.0f), 10.0f);
        cache[itr * 2] = va; cache[itr * 2 + 1] = vb;
        float hi = fmaxf(va, vb), lo = fminf(va, vb);
        if (hi > v1) { v2 = fmaxf(v1, lo); v1 = hi; }
        else v2 = fmaxf(v2, hi);
    }
    __shared__ float s1[256], s2[256];
    s1[tid] = v1; s2[tid] = v2; __syncthreads();
    for (int s = 128; s > 0; s >>= 1) {
        if (tid < s) {
            float a1 = s1[tid], a2 = s2[tid], b1v = s1[tid + s], b2v = s2[tid + s];
            s1[tid] = fmaxf(a1, b1v);
            s2[tid] = fmaxf(fminf(a1, b1v), fmaxf(a2, b2v));
        }
        __syncthreads();
    }
    const float thr = s2[0] - 0.02f * it;

    __shared__ int cands[64];
    __shared__ int ncand;
    if (tid == 0) ncand = 0;
    __syncthreads();
    #pragma unroll
    for (int itr = 0; itr < 8; itr++) {
        const int j = tid * 2 + itr * 512;
        if (cache[itr * 2] >= thr)     { int p = atomicAdd(&ncand, 1); if (p < 64) cands[p] = j; }
        if (cache[itr * 2 + 1] >= thr) { int p = atomicAdd(&ncand, 1); if (p < 64) cands[p] = j + 1; }
    }
    __syncthreads();
    const int nc = min(ncand, 64);

    __shared__ float exv[64];
    const float* irow = g_inter + (size_t)row * Id;
    for (int base = 0; base < nc; base += 8) {
        const int q = base + wid;
        if (q < nc) {
            const int j = cands[q];
            const float* wr = g_w2tf + (size_t)j * Id;
            float s = 0.0f;
            for (int k = lane; k < Id; k += 32) s += irow[k] * wr[k];
            #pragma unroll
            for (int o = 16; o > 0; o >>= 1) s += __shfl_down_sync(0xffffffffu, s, o);
            if (lane == 0) exv[q] = fminf(fmaxf((s + b2[j]) / t, -10.0f), 10.0f);
        }
    }
    __syncthreads();

    if (tid == 0) {
        float bv1 = -INFINITY, bv2 = -INFINITY;
        int bi1 = 0x7fffffff, bi2 = 0x7fffffff;
        for (int q = 0; q < nc; q++) {
            float v = exv[q]; int j = cands[q];
            if (v > bv1 || (v == bv1 && j < bi1)) {
                bv2 = bv1; bi2 = bi1; bv1 = v; bi1 = j;
            } else if (v > bv2 || (v == bv2 && j < bi2)) {
                bv2 = v; bi2 = j;
            }
        }
        float e = expf(bv2 - bv1), se = 1.0f + e;
        float w0 = 1.0f / se, w1 = e / se;
        g_tw[row] = make_float2(w0, w1);
        g_tj[row] = make_int2(bi1, bi2);
        atomicAdd(&g_usage[bi1], w0);
        atomicAdd(&g_usage[bi2], w1);
    }
}

// ---------------- layernorm -> ca0/ca1 ----------------
__global__ void __launch_bounds__(256)
ln_kernel(const float* __restrict__ gamma, const float* __restrict__ beta)
{
    const int row = blockIdx.x, tid = threadIdx.x;
    float4 v = ((const float4*)(g_proj + (size_t)row * Dd))[tid];
    float s = v.x + v.y + v.z + v.w;
    s = breduce<256>(s);
    const float mean = s * (1.0f / Dd);
    float d0 = v.x - mean, d1 = v.y - mean, d2 = v.z - mean, d3 = v.w - mean;
    float q = d0 * d0 + d1 * d1 + d2 * d2 + d3 * d3;
    q = breduce<256>(q);
    const float rs = rsqrtf(q * (1.0f / Dd) + 1e-5f);
    float4 g = ((const float4*)gamma)[tid], b = ((const float4*)beta)[tid];
    float ov[4] = { d0 * rs * g.x + b.x, d1 * rs * g.y + b.y,
                    d2 * rs * g.z + b.z, d3 * rs * g.w + b.w };
    const size_t off = (size_t)row * Dd + tid * 4;
    #pragma unroll
    for (int k = 0; k < 4; k++) {
        __half h0 = __float2half(ov[k]);
        g_ca0[off + k] = h0;
        g_ca1[off + k] = __float2half(ov[k] - __half2float(h0));
    }
}

// ---------------- diversity loss ----------------
__global__ void __launch_bounds__(512)
loss_kernel(float* __restrict__ out, int do_write)
{
    const int tid = threadIdx.x;
    float s = 0.0f;
    for (int j = tid; j < Pd; j += 512) s += g_usage[j];
    s = breduce<512>(s);
    const float denom = s + 1e-8f, uni = 1.0f / Pd;
    float q = 0.0f;
    for (int j = tid; j < Pd; j += 512) {
        float d = g_usage[j] / denom - uni;
        q += d * d;
    }
    q = breduce<512>(q);
    if (tid == 0 && do_write) out[0] = (q / Pd) * 0.01f;
}

// ---------------- launch (two-stream schedule, graph-capturable) ------------
extern "C" void kernel_launch(void* const* d_in, const int* in_sizes, int n_in,
                              void* d_out, int out_size)
{
    const int o = (n_in >= 14) ? 1 : 0;
    const float* x     = (const float*)d_in[0];
    const float* pool  = (const float*)d_in[1];
    const float* w1    = (const float*)d_in[2 + o];
    const float* b1    = (const float*)d_in[3 + o];
    const float* w2    = (const float*)d_in[4 + o];
    const float* b2    = (const float*)d_in[5 + o];
    const float* temp  = (const float*)d_in[6 + o];
    const float* wp    = (const float*)d_in[7 + o];
    const float* bp    = (const float*)d_in[8 + o];
    const float* gamma = (const float*)d_in[9 + o];
    const float* beta  = (const float*)d_in[10 + o];
    const float* wm    = (const float*)d_in[11 + o];
    const float* bm    = (const float*)d_in[12 + o];
    float* out = (float*)d_out;

    static cudaStream_t sB = nullptr;
    static cudaEvent_t evFork = nullptr, evX = nullptr, evW = nullptr,
                       evG2 = nullptr, evPW = nullptr;
    if (!sB) {
        cudaStreamCreateWithFlags(&sB, cudaStreamNonBlocking);
        cudaEventCreateWithFlags(&evFork, cudaEventDisableTiming);
        cudaEventCreateWithFlags(&evX, cudaEventDisableTiming);
        cudaEventCreateWithFlags(&evW, cudaEventDisableTiming);
        cudaEventCreateWithFlags(&evG2, cudaEventDisableTiming);
        cudaEventCreateWithFlags(&evPW, cudaEventDisableTiming);
    }

    // fork immediately: side does weight prep concurrent with main's split_x
    cudaEventRecord(evFork, 0);
    cudaStreamWaitEvent(sB, evFork, 0);

    // side: w1t, w2t, zero (needed by main) -> evW; then wp_t, wm_t
    transpose_split<<<dim3(Id / 32, Hd / 32), dim3(32, 8), 0, sB>>>(w1, Hd, Id, 3, 4, 0);
    transpose_split<<<dim3(Pd / 32, Id / 32), dim3(32, 8), 0, sB>>>(w2, Id, Pd, 7, -1, 1);
    zero_usage_kernel<<<Pd / 256, 256, 0, sB>>>();
    cudaEventRecord(evW, sB);
    transpose_split<<<dim3(Dd / 32, Hd / 32), dim3(32, 8), 0, sB>>>(wp, Hd, Dd, 8, -1, 0);
    transpose_split<<<dim3(Dd / 32, (2 * Dd) / 32), dim3(32, 8), 0, sB>>>(wm, 2 * Dd, Dd, 12, -1, 0);

    // main: split_x -> evX
    split_x2_kernel<<<((size_t)NTOK * Hd + 255) / 256, 256>>>(x);
    cudaEventRecord(evX, 0);

    // side: G3 (1-pass: x0 . wp0) -> ln
    cudaStreamWaitEvent(sB, evX, 0);
    gemm_mma<<<dim3(Dd / 128, NTOK / 128), 256, 0, sB>>>(
        0x0u, 0x8u, 1, Hd, Hd, Hd, 0, bp, nullptr, 2, Dd, 0, 0);
    ln_kernel<<<NTOK, 256, 0, sB>>>(gamma, beta);

    // main: G1 (3-pass) -> G2 (1-pass) -> evG2
    cudaStreamWaitEvent(0, evW, 0);
    gemm_mma<<<dim3(Id / 128, NTOK / 128), 256>>>(
        0x100u, 0x343u, 3, Hd, Hd, Hd, 0, b1, nullptr, 0, Id, 1, 1);
    gemm_mma<<<dim3(Pd / 128, NTOK / 128), 256>>>(
        0x6u, 0x7u, 1, Id, Id, Id, 0, b2, nullptr, 9, Pd, 0, 2);
    cudaEventRecord(evG2, 0);

    // side: pool split + poolwm (2-pass) DURING main's topk window
    cudaStreamWaitEvent(sB, evG2, 0);
    split_pool_kernel<<<((size_t)Pd * Dd + 255) / 256, 256, 0, sB>>>(pool);
    gemm_mma<<<dim3(Dd / 128, Pd / 128), 256, 0, sB>>>(
        0x52u, 0xCCu, 2, Dd, Dd, 2 * Dd, Dd, nullptr, nullptr, 3, Dd, 0, 0);
    cudaEventRecord(evPW, sB);

    // main: topk -> loss
    topk_kernel<<<NTOK, 256>>>(temp, b2);
    const long long tsz = (long long)NTOK * Dd;
    loss_kernel<<<1, 512>>>(out + tsz, ((long long)out_size > tsz) ? 1 : 0);

    // join: G4' = ln_proj @ wm1 + bm + pool-gather
    cudaStreamWaitEvent(0, evPW, 0);
    gemm_mma<<<dim3(Dd / 128, NTOK / 128), 256>>>(
        0xBAu, 0xCCu, 2, Dd, Dd, 2 * Dd, 0, bm, out, 9, Dd, 0, 3);
}